// round 10
// baseline (speedup 1.0000x reference)
#include <cuda_runtime.h>

#define NN 100000
#define EE 1600000
#define IN_DIM 128
#define HID 32
#define HEADS 4
#define OUT_DIM 40
#define NEG_SLOPE 0.2f

#define G1_ROWS 64
#define G1_SMEM ((IN_DIM*IN_DIM + G1_ROWS*IN_DIM) * (int)sizeof(float))   // 96KB
#define G2_ROWS 64
#define G2_HPAD 66
#define G2_SMEM ((IN_DIM*OUT_DIM + IN_DIM*G2_HPAD) * (int)sizeof(float))
#define SCAN_B 1024
#define NB ((NN + SCAN_B - 1) / SCAN_B)   // 98

typedef unsigned long long ull;

// ---------------- f32x2 packed-math helpers (sm_103a) ----------------
__device__ __forceinline__ ull pack2(float a, float b) {
    ull r; asm("mov.b64 %0,{%1,%2};" : "=l"(r) : "f"(a), "f"(b)); return r;
}
__device__ __forceinline__ void unpack2(ull p, float& a, float& b) {
    asm("mov.b64 {%0,%1},%2;" : "=f"(a), "=f"(b) : "l"(p));
}
__device__ __forceinline__ void ffma2(ull& acc, ull a, ull b) {
    asm("fma.rn.f32x2 %0,%1,%2,%0;" : "+l"(acc) : "l"(a), "l"(b));
}
__device__ __forceinline__ float pairsum(ull p) {
    float a, b; unpack2(p, a, b); return a + b;
}

// ---------------- scratch (device globals: allocation-free) ----------------
__device__ float g_feat1[NN * IN_DIM];
__device__ float g_el1[NN * HEADS];
__device__ float g_er1[NN * HEADS];
__device__ float g_h1[NN * IN_DIM];
__device__ float g_feat2[NN * OUT_DIM];
__device__ float g_el2[NN];
__device__ float g_er2[NN];
__device__ int   g_deg[NN];
__device__ int   g_rank[EE];
__device__ int   g_rowptr[NN + 1];
__device__ int   g_esrc[EE];
__device__ int   g_bsum[128];
__device__ int   g_boff[128];

// ---------------- zero deg ----------------
__global__ void zero_kernel() {
    int i = blockIdx.x * blockDim.x + threadIdx.x;
    if (i < NN) g_deg[i] = 0;
}

// ---- GEMM1 + fused el1/er1: k-pair FFMA2 chains (even/odd k split) ----
__global__ __launch_bounds__(256) void gemm1_kernel(const float* __restrict__ h,
                                                    const float* __restrict__ W1,
                                                    const float* __restrict__ al1,
                                                    const float* __restrict__ ar1) {
    extern __shared__ float sm[];
    float* Ws = sm;                      // [k][c] 128x128
    float* Hs = sm + IN_DIM * IN_DIM;    // [r][k] 64x128
    int t = threadIdx.x;
    int row0 = blockIdx.x * G1_ROWS;

    const float4* W4 = (const float4*)W1;
    float4* Ws4 = (float4*)Ws;
    for (int i = t; i < IN_DIM * IN_DIM / 4; i += 256) Ws4[i] = W4[i];

    float4* Hs4 = (float4*)Hs;
    const float4* H4 = (const float4*)h;
    for (int i = t; i < G1_ROWS * IN_DIM / 4; i += 256) {
        int r = i >> 5, c = i & 31;
        int g = row0 + r;
        Hs4[i] = (g < NN) ? H4[g * 32 + c] : make_float4(0.f, 0.f, 0.f, 0.f);
    }
    __syncthreads();

    int cg = t & 31;   // lane: cols 4cg..4cg+3
    int rg = t >> 5;   // warp: rows rg*8..rg*8+7
    ull acc[8][4];     // [row][col]; lo = even-k chain, hi = odd-k chain
    #pragma unroll
    for (int r = 0; r < 8; ++r)
        #pragma unroll
        for (int c = 0; c < 4; ++c) acc[r][c] = 0ull;

    const float* Hrow = Hs + rg * 8 * IN_DIM;
    #pragma unroll 1
    for (int kb = 0; kb < IN_DIM; kb += 4) {
        float4 w0 = ((const float4*)(Ws + (kb + 0) * IN_DIM))[cg];
        float4 w1 = ((const float4*)(Ws + (kb + 1) * IN_DIM))[cg];
        float4 w2 = ((const float4*)(Ws + (kb + 2) * IN_DIM))[cg];
        float4 w3 = ((const float4*)(Ws + (kb + 3) * IN_DIM))[cg];
        ull wax = pack2(w0.x, w1.x), way = pack2(w0.y, w1.y);
        ull waz = pack2(w0.z, w1.z), waw = pack2(w0.w, w1.w);
        ull wbx = pack2(w2.x, w3.x), wby = pack2(w2.y, w3.y);
        ull wbz = pack2(w2.z, w3.z), wbw = pack2(w2.w, w3.w);
        #pragma unroll
        for (int r = 0; r < 8; ++r) {
            ulonglong2 hq = *(const ulonglong2*)(Hrow + r * IN_DIM + kb);
            ffma2(acc[r][0], hq.x, wax); ffma2(acc[r][1], hq.x, way);
            ffma2(acc[r][2], hq.x, waz); ffma2(acc[r][3], hq.x, waw);
            ffma2(acc[r][0], hq.y, wbx); ffma2(acc[r][1], hq.y, wby);
            ffma2(acc[r][2], hq.y, wbz); ffma2(acc[r][3], hq.y, wbw);
        }
    }

    float4 al = ((const float4*)al1)[cg];
    float4 ar = ((const float4*)ar1)[cg];
    int hh = cg >> 3;

    #pragma unroll
    for (int r = 0; r < 8; ++r) {
        int g = row0 + rg * 8 + r;     // uniform across warp
        if (g >= NN) continue;
        float c0 = pairsum(acc[r][0]);
        float c1 = pairsum(acc[r][1]);
        float c2 = pairsum(acc[r][2]);
        float c3 = pairsum(acc[r][3]);
        ((float4*)g_feat1)[g * 32 + cg] = make_float4(c0, c1, c2, c3);
        float p = c0 * al.x + c1 * al.y + c2 * al.z + c3 * al.w;
        float q = c0 * ar.x + c1 * ar.y + c2 * ar.z + c3 * ar.w;
        p += __shfl_xor_sync(0xFFFFFFFFu, p, 1);
        p += __shfl_xor_sync(0xFFFFFFFFu, p, 2);
        p += __shfl_xor_sync(0xFFFFFFFFu, p, 4);
        q += __shfl_xor_sync(0xFFFFFFFFu, q, 1);
        q += __shfl_xor_sync(0xFFFFFFFFu, q, 2);
        q += __shfl_xor_sync(0xFFFFFFFFu, q, 4);
        if ((cg & 7) == 0) {
            g_el1[g * 4 + hh] = p;
            g_er1[g * 4 + hh] = q;
        }
    }
}

// ---------------- CSR build ----------------
__global__ void hist_kernel(const int* __restrict__ dst) {
    int i = blockIdx.x * blockDim.x + threadIdx.x;
    if (i < EE) g_rank[i] = atomicAdd(&g_deg[dst[i]], 1);
}

__global__ void scan1_kernel() {
    __shared__ int ws[32];
    int t = threadIdx.x;
    int lane = t & 31, wp = t >> 5;
    int i = blockIdx.x * SCAN_B + t;
    int v = (i < NN) ? g_deg[i] : 0;
    int x = v;
    #pragma unroll
    for (int off = 1; off < 32; off <<= 1) {
        int y = __shfl_up_sync(0xFFFFFFFFu, x, off);
        if (lane >= off) x += y;
    }
    if (lane == 31) ws[wp] = x;
    __syncthreads();
    if (wp == 0) {
        int o = ws[lane];
        int s = o;
        #pragma unroll
        for (int off = 1; off < 32; off <<= 1) {
            int y = __shfl_up_sync(0xFFFFFFFFu, s, off);
            if (lane >= off) s += y;
        }
        ws[lane] = s - o;      // exclusive prefix of warp sums
    }
    __syncthreads();
    int base = ws[wp];
    if (i < NN) g_rowptr[i] = x - v + base;
    if (t == SCAN_B - 1) g_bsum[blockIdx.x] = x + base;
}

__global__ void scan2_kernel() {    // 128 threads, scan NB=98 block sums
    int t = threadIdx.x;
    int lane = t & 31, wp = t >> 5;
    int v = (t < NB) ? g_bsum[t] : 0;
    int x = v;
    #pragma unroll
    for (int off = 1; off < 32; off <<= 1) {
        int y = __shfl_up_sync(0xFFFFFFFFu, x, off);
        if (lane >= off) x += y;
    }
    __shared__ int wsum[4];
    if (lane == 31) wsum[wp] = x;
    __syncthreads();
    int add = 0;
    for (int w = 0; w < wp; ++w) add += wsum[w];
    if (t < NB) g_boff[t] = x - v + add;   // exclusive
}

__global__ void scan3_kernel() {
    int i = blockIdx.x * SCAN_B + threadIdx.x;
    if (i < NN) g_rowptr[i] += g_boff[blockIdx.x];
    if (i == 0) g_rowptr[NN] = EE;
}

__global__ void scatter_kernel(const int* __restrict__ src, const int* __restrict__ dst) {
    int i = blockIdx.x * blockDim.x + threadIdx.x;
    if (i < EE) {
        int d = dst[i];
        g_esrc[g_rowptr[d] + g_rank[i]] = src[i];
    }
}

// ------- layer-1 aggregation: warp/node, single pass, 4-edge unroll -------
__global__ __launch_bounds__(256) void agg1_kernel(const float* __restrict__ b1) {
    int n = (blockIdx.x * blockDim.x + threadIdx.x) >> 5;
    int l = threadIdx.x & 31;
    if (n >= NN) return;
    int hh = l >> 3;
    float erh = g_er1[n * 4 + hh];
    int s0 = g_rowptr[n], s1 = g_rowptr[n + 1];

    const ulonglong2* f2 = (const ulonglong2*)g_feat1;
    ull aA0 = 0, aA1 = 0, aB0 = 0, aB1 = 0;
    float dsA = 0.f, dsB = 0.f;

    int i = s0;
    for (; i + 4 <= s1; i += 4) {
        int sa = g_esrc[i];
        int sb = g_esrc[i + 1];
        int sc = g_esrc[i + 2];
        int sd = g_esrc[i + 3];
        float ea = g_el1[sa * 4 + hh] + erh;
        float eb = g_el1[sb * 4 + hh] + erh;
        float ec = g_el1[sc * 4 + hh] + erh;
        float ed = g_el1[sd * 4 + hh] + erh;
        ulonglong2 fa = f2[sa * 32 + l];
        ulonglong2 fb = f2[sb * 32 + l];
        ulonglong2 fc = f2[sc * 32 + l];
        ulonglong2 fd = f2[sd * 32 + l];
        ea = fmaxf(ea, NEG_SLOPE * ea);
        eb = fmaxf(eb, NEG_SLOPE * eb);
        ec = fmaxf(ec, NEG_SLOPE * ec);
        ed = fmaxf(ed, NEG_SLOPE * ed);
        float wa = __expf(ea), wb = __expf(eb);
        float wc = __expf(ec), wd = __expf(ed);
        ull wa2 = pack2(wa, wa), wb2 = pack2(wb, wb);
        ull wc2 = pack2(wc, wc), wd2 = pack2(wd, wd);
        ffma2(aA0, wa2, fa.x); ffma2(aA1, wa2, fa.y);
        ffma2(aB0, wb2, fb.x); ffma2(aB1, wb2, fb.y);
        ffma2(aA0, wc2, fc.x); ffma2(aA1, wc2, fc.y);
        ffma2(aB0, wd2, fd.x); ffma2(aB1, wd2, fd.y);
        dsA += wa + wc; dsB += wb + wd;
    }
    for (; i < s1; ++i) {
        int sa = g_esrc[i];
        float ea = g_el1[sa * 4 + hh] + erh;
        ea = fmaxf(ea, NEG_SLOPE * ea);
        float wa = __expf(ea);
        ulonglong2 fa = f2[sa * 32 + l];
        ull wa2 = pack2(wa, wa);
        ffma2(aA0, wa2, fa.x); ffma2(aA1, wa2, fa.y);
        dsA += wa;
    }

    float inv = 1.0f / fmaxf(dsA + dsB, 1e-9f);
    float xA, yA, xB, yB, zA, wA, zB, wB;
    unpack2(aA0, xA, yA); unpack2(aB0, xB, yB);
    unpack2(aA1, zA, wA); unpack2(aB1, zB, wB);
    float4 bb = ((const float4*)b1)[l];
    float4 o;
    o.x = fmaxf((xA + xB) * inv + bb.x, 0.f);
    o.y = fmaxf((yA + yB) * inv + bb.y, 0.f);
    o.z = fmaxf((zA + zB) * inv + bb.z, 0.f);
    o.w = fmaxf((wA + wB) * inv + bb.w, 0.f);
    ((float4*)g_h1)[n * 32 + l] = o;
}

// ------- GEMM2 + fused el2/er2: f32x2, 8 rows/warp, transposed H tile -----
__global__ __launch_bounds__(256) void gemm2_kernel(const float* __restrict__ W2,
                                                    const float* __restrict__ al2,
                                                    const float* __restrict__ ar2) {
    extern __shared__ float sm[];
    float* Ws  = sm;                           // 128*40
    float* HsT = sm + IN_DIM * OUT_DIM;        // [k][r] padded stride 66
    int t = threadIdx.x;
    int row0 = blockIdx.x * G2_ROWS;

    for (int i = t; i < IN_DIM * OUT_DIM; i += 256) Ws[i] = W2[i];

    const float4* H4 = (const float4*)g_h1;
    for (int i = t; i < G2_ROWS * IN_DIM / 4; i += 256) {
        int r = i >> 5, c4 = i & 31;
        int g = row0 + r;
        float4 f = (g < NN) ? H4[g * 32 + c4] : make_float4(0.f, 0.f, 0.f, 0.f);
        HsT[(4 * c4 + 0) * G2_HPAD + r] = f.x;
        HsT[(4 * c4 + 1) * G2_HPAD + r] = f.y;
        HsT[(4 * c4 + 2) * G2_HPAD + r] = f.z;
        HsT[(4 * c4 + 3) * G2_HPAD + r] = f.w;
    }
    __syncthreads();

    int l = t & 31;
    int wr = (t >> 5) * 8;
    bool hi = (l < 8);
    float a0 = __ldg(al2 + l), r0 = __ldg(ar2 + l);
    float a1 = hi ? __ldg(al2 + 32 + l) : 0.f;
    float r1 = hi ? __ldg(ar2 + 32 + l) : 0.f;

    ull acc[4][2];
    #pragma unroll
    for (int rp = 0; rp < 4; ++rp) { acc[rp][0] = 0ull; acc[rp][1] = 0ull; }

    #pragma unroll 2
    for (int k = 0; k < IN_DIM; ++k) {
        float w0 = Ws[k * OUT_DIM + l];
        float w1 = hi ? Ws[k * OUT_DIM + 32 + l] : 0.f;
        ull w02 = pack2(w0, w0), w12 = pack2(w1, w1);
        const ull* hp = (const ull*)(HsT + k * G2_HPAD + wr);
        #pragma unroll
        for (int rp = 0; rp < 4; ++rp) {
            ull h2 = hp[rp];
            ffma2(acc[rp][0], h2, w02);
            ffma2(acc[rp][1], h2, w12);
        }
    }

    #pragma unroll
    for (int rp = 0; rp < 4; ++rp) {
        float v0a, v0b, v1a, v1b;
        unpack2(acc[rp][0], v0a, v0b);
        unpack2(acc[rp][1], v1a, v1b);
        #pragma unroll
        for (int half = 0; half < 2; ++half) {
            int g = row0 + wr + 2 * rp + half;   // uniform per warp
            float v0 = half ? v0b : v0a;
            float v1 = half ? v1b : v1a;
            if (g < NN) {
                g_feat2[g * OUT_DIM + l] = v0;
                if (hi) g_feat2[g * OUT_DIM + 32 + l] = v1;
            }
            float p = v0 * a0 + v1 * a1;
            float q = v0 * r0 + v1 * r1;
            #pragma unroll
            for (int off = 16; off >= 1; off >>= 1) {
                p += __shfl_xor_sync(0xFFFFFFFFu, p, off);
                q += __shfl_xor_sync(0xFFFFFFFFu, q, off);
            }
            if (g < NN && l == 0) { g_el2[g] = p; g_er2[g] = q; }
        }
    }
}

// ------- layer-2 aggregation: warp/node, single pass, 4-edge unroll -------
__global__ __launch_bounds__(256) void agg2_kernel(const float* __restrict__ b2, float* __restrict__ out) {
    int n = (blockIdx.x * blockDim.x + threadIdx.x) >> 5;
    int l = threadIdx.x & 31;
    if (n >= NN) return;
    float er = g_er2[n];
    int s0 = g_rowptr[n], s1 = g_rowptr[n + 1];
    int lc = (l < 20) ? l : 19;          // lanes 20-31 shadow lane 19 (unused)

    const ull* f2 = (const ull*)g_feat2;  // row = 20 ull
    ull aA = 0, aB = 0;
    float dsA = 0.f, dsB = 0.f;

    int i = s0;
    for (; i + 4 <= s1; i += 4) {
        int sa = g_esrc[i];
        int sb = g_esrc[i + 1];
        int sc = g_esrc[i + 2];
        int sd = g_esrc[i + 3];
        float ea = g_el2[sa] + er;
        float eb = g_el2[sb] + er;
        float ec = g_el2[sc] + er;
        float ed = g_el2[sd] + er;
        ull fa = f2[sa * 20 + lc];
        ull fb = f2[sb * 20 + lc];
        ull fc = f2[sc * 20 + lc];
        ull fd = f2[sd * 20 + lc];
        ea = fmaxf(ea, NEG_SLOPE * ea);
        eb = fmaxf(eb, NEG_SLOPE * eb);
        ec = fmaxf(ec, NEG_SLOPE * ec);
        ed = fmaxf(ed, NEG_SLOPE * ed);
        float wa = __expf(ea), wb = __expf(eb);
        float wc = __expf(ec), wd = __expf(ed);
        ffma2(aA, pack2(wa, wa), fa);
        ffma2(aB, pack2(wb, wb), fb);
        ffma2(aA, pack2(wc, wc), fc);
        ffma2(aB, pack2(wd, wd), fd);
        dsA += wa + wc; dsB += wb + wd;
    }
    for (; i < s1; ++i) {
        int sa = g_esrc[i];
        float ea = g_el2[sa] + er;
        ea = fmaxf(ea, NEG_SLOPE * ea);
        float wa = __expf(ea);
        ffma2(aA, pack2(wa, wa), f2[sa * 20 + lc]);
        dsA += wa;
    }

    if (l < 20) {
        float inv = 1.0f / fmaxf(dsA + dsB, 1e-9f);
        float xa, ya, xb, yb;
        unpack2(aA, xa, ya); unpack2(aB, xb, yb);
        float o0 = (xa + xb) * inv + b2[2 * l];
        float o1 = (ya + yb) * inv + b2[2 * l + 1];
        ((ull*)out)[n * 20 + l] = pack2(o0, o1);
    }
}

// ---------------- side stream for CSR/GEMM1 overlap ----------------
namespace {
struct Aux {
    cudaStream_t s2;
    cudaEvent_t fork, join;
    bool ok;
    Aux() : s2(nullptr), fork(nullptr), join(nullptr), ok(false) {
        if (cudaStreamCreateWithFlags(&s2, cudaStreamNonBlocking) != cudaSuccess) return;
        if (cudaEventCreateWithFlags(&fork, cudaEventDisableTiming) != cudaSuccess) return;
        if (cudaEventCreateWithFlags(&join, cudaEventDisableTiming) != cudaSuccess) return;
        ok = true;
    }
};
Aux g_aux;
}

// ---------------- launch ----------------
extern "C" void kernel_launch(void* const* d_in, const int* in_sizes, int n_in,
                              void* d_out, int out_size) {
    const float* h   = (const float*)d_in[0];
    const int*   src = (const int*)  d_in[1];
    const int*   dst = (const int*)  d_in[2];
    const float* W1  = (const float*)d_in[3];
    const float* al1 = (const float*)d_in[4];
    const float* ar1 = (const float*)d_in[5];
    const float* b1  = (const float*)d_in[6];
    const float* W2  = (const float*)d_in[7];
    const float* al2 = (const float*)d_in[8];
    const float* ar2 = (const float*)d_in[9];
    const float* b2  = (const float*)d_in[10];
    float* out = (float*)d_out;

    cudaFuncSetAttribute(gemm1_kernel, cudaFuncAttributeMaxDynamicSharedMemorySize, G1_SMEM);
    cudaFuncSetAttribute(gemm2_kernel, cudaFuncAttributeMaxDynamicSharedMemorySize, G2_SMEM);

    int nwarp_blocks = (NN * 32 + 255) / 256;
    int eblocks = (EE + 255) / 256;

    if (g_aux.ok) {
        // fork: CSR build on side stream, GEMM1 on main stream (issued 4th for ncu).
        cudaEventRecord(g_aux.fork, 0);
        cudaStreamWaitEvent(g_aux.s2, g_aux.fork, 0);
        zero_kernel<<<(NN + 255) / 256, 256, 0, g_aux.s2>>>();            // 1
        hist_kernel<<<eblocks, 256, 0, g_aux.s2>>>(dst);                  // 2
        scan1_kernel<<<NB, SCAN_B, 0, g_aux.s2>>>();                      // 3
        gemm1_kernel<<<(NN + G1_ROWS - 1) / G1_ROWS, 256, G1_SMEM>>>(h, W1, al1, ar1);  // 4
        scan2_kernel<<<1, 128, 0, g_aux.s2>>>();                          // 5
        scan3_kernel<<<NB, SCAN_B, 0, g_aux.s2>>>();                      // 6
        scatter_kernel<<<eblocks, 256, 0, g_aux.s2>>>(src, dst);          // 7
        cudaEventRecord(g_aux.join, g_aux.s2);
        cudaStreamWaitEvent(0, g_aux.join, 0);
    } else {
        zero_kernel<<<(NN + 255) / 256, 256>>>();
        hist_kernel<<<eblocks, 256>>>(dst);
        scan1_kernel<<<NB, SCAN_B>>>();
        gemm1_kernel<<<(NN + G1_ROWS - 1) / G1_ROWS, 256, G1_SMEM>>>(h, W1, al1, ar1);
        scan2_kernel<<<1, 128>>>();
        scan3_kernel<<<NB, SCAN_B>>>();
        scatter_kernel<<<eblocks, 256>>>(src, dst);
    }

    agg1_kernel<<<nwarp_blocks, 256>>>(b1);
    gemm2_kernel<<<(NN + G2_ROWS - 1) / G2_ROWS, 256, G2_SMEM>>>(W2, al2, ar2);
    agg2_kernel<<<nwarp_blocks, 256>>>(b2, out);
}

// round 11
// speedup vs baseline: 1.2609x; 1.2609x over previous
#include <cuda_runtime.h>
#include <cuda_fp16.h>

#define NN 100000
#define EE 1600000
#define IN_DIM 128
#define HID 32
#define HEADS 4
#define OUT_DIM 40
#define NEG_SLOPE 0.2f

#define G1_ROWS 64
#define A_STRIDE 136                                  // fp16 elems, +8 pad kills LDSM conflicts
#define G1_SMEM ((G1_ROWS*A_STRIDE + IN_DIM*A_STRIDE) * 2)   // 52224 B
#define G2_ROWS 64
#define G2_HPAD 66
#define G2_SMEM ((IN_DIM*OUT_DIM + IN_DIM*G2_HPAD) * (int)sizeof(float))
#define SCAN_B 1024
#define NB ((NN + SCAN_B - 1) / SCAN_B)   // 98

typedef unsigned long long ull;
typedef unsigned int uint;

// ---------------- f32x2 packed-math helpers (sm_103a) ----------------
__device__ __forceinline__ ull pack2(float a, float b) {
    ull r; asm("mov.b64 %0,{%1,%2};" : "=l"(r) : "f"(a), "f"(b)); return r;
}
__device__ __forceinline__ void unpack2(ull p, float& a, float& b) {
    asm("mov.b64 {%0,%1},%2;" : "=f"(a), "=f"(b) : "l"(p));
}
__device__ __forceinline__ void ffma2(ull& acc, ull a, ull b) {
    asm("fma.rn.f32x2 %0,%1,%2,%0;" : "+l"(acc) : "l"(a), "l"(b));
}

// ---------------- scratch (device globals: allocation-free) ----------------
__device__ float  g_feat1[NN * IN_DIM];
__device__ float  g_el1[NN * HEADS];
__device__ float  g_er1[NN * HEADS];
__device__ float  g_h1[NN * IN_DIM];
__device__ float  g_feat2[NN * OUT_DIM];
__device__ float  g_el2[NN];
__device__ float  g_er2[NN];
__device__ __half g_W1h[IN_DIM * IN_DIM];
__device__ int    g_deg[NN];
__device__ int    g_rank[EE];
__device__ int    g_rowptr[NN + 1];
__device__ int    g_esrc[EE];
__device__ int    g_bsum[128];
__device__ int    g_boff[128];

// ---------------- zero deg ----------------
__global__ void zero_kernel() {
    int i = blockIdx.x * blockDim.x + threadIdx.x;
    if (i < NN) g_deg[i] = 0;
}

// ---------------- W1 fp32 -> fp16 (once per launch) ----------------
__global__ void w1cvt_kernel(const float* __restrict__ W1) {
    int i = blockIdx.x * blockDim.x + threadIdx.x;   // 8192 float2s
    if (i < IN_DIM * IN_DIM / 2) {
        float2 f = ((const float2*)W1)[i];
        ((__half2*)g_W1h)[i] = __floats2half2_rn(f.x, f.y);
    }
}

// ---- GEMM1 on tensor cores: fp16 mma.m16n8k16, fp32 accum, fused el1/er1 ----
__global__ __launch_bounds__(256) void gemm1_kernel(const float* __restrict__ h,
                                                    const float* __restrict__ al1,
                                                    const float* __restrict__ ar1) {
    extern __shared__ __half smh[];
    __half* As = smh;                          // [64][A_STRIDE]
    __half* Ws = smh + G1_ROWS * A_STRIDE;     // [128][A_STRIDE]
    int t = threadIdx.x;
    int row0 = blockIdx.x * G1_ROWS;

    // load W1 (pre-converted fp16): 128x128, 8 halfs per thread-step
    for (int i = t; i < IN_DIM * IN_DIM / 8; i += 256) {
        int r = i >> 4, c8 = i & 15;
        uint4 v = ((const uint4*)g_W1h)[i];
        *(uint4*)(Ws + r * A_STRIDE + c8 * 8) = v;
    }
    // load + convert h tile: 64x128 fp32 -> fp16
    const float4* H4 = (const float4*)h;
    for (int i = t; i < G1_ROWS * IN_DIM / 4; i += 256) {
        int r = i >> 5, c4 = i & 31;
        int g = row0 + r;
        float4 f = (g < NN) ? H4[g * 32 + c4] : make_float4(0.f, 0.f, 0.f, 0.f);
        __half2 lo = __floats2half2_rn(f.x, f.y);
        __half2 hi = __floats2half2_rn(f.z, f.w);
        uint2 v;
        v.x = *(uint*)&lo; v.y = *(uint*)&hi;
        *(uint2*)(As + r * A_STRIDE + c4 * 4) = v;
    }
    __syncthreads();

    int w = t >> 5, lane = t & 31;
    int rw = (w & 3) * 16;          // warp's 16 rows within tile
    int ch = (w >> 2) * 64;         // warp's 64-col half

    // ldmatrix base addresses
    uint a_base = (uint)__cvta_generic_to_shared(
        As + (rw + (lane & 15)) * A_STRIDE + ((lane >> 4) * 8));
    uint b_base = (uint)__cvta_generic_to_shared(
        Ws + (lane & 15) * A_STRIDE + ch + ((lane >> 4) * 8));

    float acc[8][4];
    #pragma unroll
    for (int j = 0; j < 8; ++j)
        #pragma unroll
        for (int c = 0; c < 4; ++c) acc[j][c] = 0.f;

    #pragma unroll
    for (int kb = 0; kb < 8; ++kb) {
        uint a0, a1, a2, a3;
        asm volatile("ldmatrix.sync.aligned.m8n8.x4.shared.b16 {%0,%1,%2,%3}, [%4];"
                     : "=r"(a0), "=r"(a1), "=r"(a2), "=r"(a3)
                     : "r"(a_base + kb * 32));                      // 16 fp16 = 32B per k-step
        #pragma unroll
        for (int p = 0; p < 4; ++p) {                               // n-tile pairs
            uint b0, b1, b2, b3;
            asm volatile("ldmatrix.sync.aligned.m8n8.x4.trans.shared.b16 {%0,%1,%2,%3}, [%4];"
                         : "=r"(b0), "=r"(b1), "=r"(b2), "=r"(b3)
                         : "r"(b_base + kb * 16 * A_STRIDE * 2 + p * 32));
            asm volatile("mma.sync.aligned.m16n8k16.row.col.f32.f16.f16.f32 "
                         "{%0,%1,%2,%3}, {%4,%5,%6,%7}, {%8,%9}, {%0,%1,%2,%3};"
                         : "+f"(acc[2*p][0]), "+f"(acc[2*p][1]), "+f"(acc[2*p][2]), "+f"(acc[2*p][3])
                         : "r"(a0), "r"(a1), "r"(a2), "r"(a3), "r"(b0), "r"(b1));
            asm volatile("mma.sync.aligned.m16n8k16.row.col.f32.f16.f16.f32 "
                         "{%0,%1,%2,%3}, {%4,%5,%6,%7}, {%8,%9}, {%0,%1,%2,%3};"
                         : "+f"(acc[2*p+1][0]), "+f"(acc[2*p+1][1]), "+f"(acc[2*p+1][2]), "+f"(acc[2*p+1][3])
                         : "r"(a0), "r"(a1), "r"(a2), "r"(a3), "r"(b2), "r"(b3));
        }
    }

    // ---- epilogue: store feat1 fp32 + fused per-head el/er ----
    int g0 = lane >> 2, quad = lane & 3;
    int r0g = row0 + rw + g0;          // fragment row 0
    int r1g = r0g + 8;                 // fragment row 1
    int h0 = (w >> 2) * 2;             // first head of this col-half

    float pe[2][2] = {{0.f, 0.f}, {0.f, 0.f}};   // [head][row]
    float pr[2][2] = {{0.f, 0.f}, {0.f, 0.f}};

    #pragma unroll
    for (int j = 0; j < 8; ++j) {
        int n0 = ch + j * 8 + quad * 2;
        float2 av = *(const float2*)(al1 + n0);
        float2 rv = *(const float2*)(ar1 + n0);
        if (r0g < NN) *(float2*)(g_feat1 + r0g * IN_DIM + n0) = make_float2(acc[j][0], acc[j][1]);
        if (r1g < NN) *(float2*)(g_feat1 + r1g * IN_DIM + n0) = make_float2(acc[j][2], acc[j][3]);
        int hi = j >> 2;
        pe[hi][0] += acc[j][0] * av.x + acc[j][1] * av.y;
        pe[hi][1] += acc[j][2] * av.x + acc[j][3] * av.y;
        pr[hi][0] += acc[j][0] * rv.x + acc[j][1] * rv.y;
        pr[hi][1] += acc[j][2] * rv.x + acc[j][3] * rv.y;
    }
    #pragma unroll
    for (int hi = 0; hi < 2; ++hi)
        #pragma unroll
        for (int rr = 0; rr < 2; ++rr) {
            float e = pe[hi][rr], r = pr[hi][rr];
            e += __shfl_xor_sync(0xFFFFFFFFu, e, 1);
            e += __shfl_xor_sync(0xFFFFFFFFu, e, 2);
            r += __shfl_xor_sync(0xFFFFFFFFu, r, 1);
            r += __shfl_xor_sync(0xFFFFFFFFu, r, 2);
            int g = rr ? r1g : r0g;
            if (quad == 0 && g < NN) {
                g_el1[g * 4 + h0 + hi] = e;
                g_er1[g * 4 + h0 + hi] = r;
            }
        }
}

// ---------------- CSR build ----------------
__global__ void hist_kernel(const int* __restrict__ dst) {
    int i = blockIdx.x * blockDim.x + threadIdx.x;
    if (i < EE) g_rank[i] = atomicAdd(&g_deg[dst[i]], 1);
}

__global__ void scan1_kernel() {
    __shared__ int ws[32];
    int t = threadIdx.x;
    int lane = t & 31, wp = t >> 5;
    int i = blockIdx.x * SCAN_B + t;
    int v = (i < NN) ? g_deg[i] : 0;
    int x = v;
    #pragma unroll
    for (int off = 1; off < 32; off <<= 1) {
        int y = __shfl_up_sync(0xFFFFFFFFu, x, off);
        if (lane >= off) x += y;
    }
    if (lane == 31) ws[wp] = x;
    __syncthreads();
    if (wp == 0) {
        int o = ws[lane];
        int s = o;
        #pragma unroll
        for (int off = 1; off < 32; off <<= 1) {
            int y = __shfl_up_sync(0xFFFFFFFFu, s, off);
            if (lane >= off) s += y;
        }
        ws[lane] = s - o;
    }
    __syncthreads();
    int base = ws[wp];
    if (i < NN) g_rowptr[i] = x - v + base;
    if (t == SCAN_B - 1) g_bsum[blockIdx.x] = x + base;
}

__global__ void scan2_kernel() {
    int t = threadIdx.x;
    int lane = t & 31, wp = t >> 5;
    int v = (t < NB) ? g_bsum[t] : 0;
    int x = v;
    #pragma unroll
    for (int off = 1; off < 32; off <<= 1) {
        int y = __shfl_up_sync(0xFFFFFFFFu, x, off);
        if (lane >= off) x += y;
    }
    __shared__ int wsum[4];
    if (lane == 31) wsum[wp] = x;
    __syncthreads();
    int add = 0;
    for (int w = 0; w < wp; ++w) add += wsum[w];
    if (t < NB) g_boff[t] = x - v + add;
}

__global__ void scan3_kernel() {
    int i = blockIdx.x * SCAN_B + threadIdx.x;
    if (i < NN) g_rowptr[i] += g_boff[blockIdx.x];
    if (i == 0) g_rowptr[NN] = EE;
}

__global__ void scatter_kernel(const int* __restrict__ src, const int* __restrict__ dst) {
    int i = blockIdx.x * blockDim.x + threadIdx.x;
    if (i < EE) {
        int d = dst[i];
        g_esrc[g_rowptr[d] + g_rank[i]] = src[i];
    }
}

// ------- layer-1 aggregation: warp/node, single pass, 4-edge unroll -------
__global__ __launch_bounds__(256) void agg1_kernel(const float* __restrict__ b1) {
    int n = (blockIdx.x * blockDim.x + threadIdx.x) >> 5;
    int l = threadIdx.x & 31;
    if (n >= NN) return;
    int hh = l >> 3;
    float erh = g_er1[n * 4 + hh];
    int s0 = g_rowptr[n], s1 = g_rowptr[n + 1];

    const ulonglong2* f2 = (const ulonglong2*)g_feat1;
    ull aA0 = 0, aA1 = 0, aB0 = 0, aB1 = 0;
    float dsA = 0.f, dsB = 0.f;

    int i = s0;
    for (; i + 4 <= s1; i += 4) {
        int sa = g_esrc[i];
        int sb = g_esrc[i + 1];
        int sc = g_esrc[i + 2];
        int sd = g_esrc[i + 3];
        float ea = g_el1[sa * 4 + hh] + erh;
        float eb = g_el1[sb * 4 + hh] + erh;
        float ec = g_el1[sc * 4 + hh] + erh;
        float ed = g_el1[sd * 4 + hh] + erh;
        ulonglong2 fa = f2[sa * 32 + l];
        ulonglong2 fb = f2[sb * 32 + l];
        ulonglong2 fc = f2[sc * 32 + l];
        ulonglong2 fd = f2[sd * 32 + l];
        ea = fmaxf(ea, NEG_SLOPE * ea);
        eb = fmaxf(eb, NEG_SLOPE * eb);
        ec = fmaxf(ec, NEG_SLOPE * ec);
        ed = fmaxf(ed, NEG_SLOPE * ed);
        float wa = __expf(ea), wb = __expf(eb);
        float wc = __expf(ec), wd = __expf(ed);
        ull wa2 = pack2(wa, wa), wb2 = pack2(wb, wb);
        ull wc2 = pack2(wc, wc), wd2 = pack2(wd, wd);
        ffma2(aA0, wa2, fa.x); ffma2(aA1, wa2, fa.y);
        ffma2(aB0, wb2, fb.x); ffma2(aB1, wb2, fb.y);
        ffma2(aA0, wc2, fc.x); ffma2(aA1, wc2, fc.y);
        ffma2(aB0, wd2, fd.x); ffma2(aB1, wd2, fd.y);
        dsA += wa + wc; dsB += wb + wd;
    }
    for (; i < s1; ++i) {
        int sa = g_esrc[i];
        float ea = g_el1[sa * 4 + hh] + erh;
        ea = fmaxf(ea, NEG_SLOPE * ea);
        float wa = __expf(ea);
        ulonglong2 fa = f2[sa * 32 + l];
        ull wa2 = pack2(wa, wa);
        ffma2(aA0, wa2, fa.x); ffma2(aA1, wa2, fa.y);
        dsA += wa;
    }

    float inv = 1.0f / fmaxf(dsA + dsB, 1e-9f);
    float xA, yA, xB, yB, zA, wA, zB, wB;
    unpack2(aA0, xA, yA); unpack2(aB0, xB, yB);
    unpack2(aA1, zA, wA); unpack2(aB1, zB, wB);
    float4 bb = ((const float4*)b1)[l];
    float4 o;
    o.x = fmaxf((xA + xB) * inv + bb.x, 0.f);
    o.y = fmaxf((yA + yB) * inv + bb.y, 0.f);
    o.z = fmaxf((zA + zB) * inv + bb.z, 0.f);
    o.w = fmaxf((wA + wB) * inv + bb.w, 0.f);
    ((float4*)g_h1)[n * 32 + l] = o;
}

// ------- GEMM2 + fused el2/er2: f32x2, 8 rows/warp, transposed H tile -----
__global__ __launch_bounds__(256) void gemm2_kernel(const float* __restrict__ W2,
                                                    const float* __restrict__ al2,
                                                    const float* __restrict__ ar2) {
    extern __shared__ float sm[];
    float* Ws  = sm;                           // 128*40
    float* HsT = sm + IN_DIM * OUT_DIM;        // [k][r] padded stride 66
    int t = threadIdx.x;
    int row0 = blockIdx.x * G2_ROWS;

    for (int i = t; i < IN_DIM * OUT_DIM; i += 256) Ws[i] = W2[i];

    const float4* H4 = (const float4*)g_h1;
    for (int i = t; i < G2_ROWS * IN_DIM / 4; i += 256) {
        int r = i >> 5, c4 = i & 31;
        int g = row0 + r;
        float4 f = (g < NN) ? H4[g * 32 + c4] : make_float4(0.f, 0.f, 0.f, 0.f);
        HsT[(4 * c4 + 0) * G2_HPAD + r] = f.x;
        HsT[(4 * c4 + 1) * G2_HPAD + r] = f.y;
        HsT[(4 * c4 + 2) * G2_HPAD + r] = f.z;
        HsT[(4 * c4 + 3) * G2_HPAD + r] = f.w;
    }
    __syncthreads();

    int l = t & 31;
    int wr = (t >> 5) * 8;
    bool hi = (l < 8);
    float a0 = __ldg(al2 + l), r0 = __ldg(ar2 + l);
    float a1 = hi ? __ldg(al2 + 32 + l) : 0.f;
    float r1 = hi ? __ldg(ar2 + 32 + l) : 0.f;

    ull acc[4][2];
    #pragma unroll
    for (int rp = 0; rp < 4; ++rp) { acc[rp][0] = 0ull; acc[rp][1] = 0ull; }

    #pragma unroll 2
    for (int k = 0; k < IN_DIM; ++k) {
        float w0 = Ws[k * OUT_DIM + l];
        float w1 = hi ? Ws[k * OUT_DIM + 32 + l] : 0.f;
        ull w02 = pack2(w0, w0), w12 = pack2(w1, w1);
        const ull* hp = (const ull*)(HsT + k * G2_HPAD + wr);
        #pragma unroll
        for (int rp = 0; rp < 4; ++rp) {
            ull h2 = hp[rp];
            ffma2(acc[rp][0], h2, w02);
            ffma2(acc[rp][1], h2, w12);
        }
    }

    #pragma unroll
    for (int rp = 0; rp < 4; ++rp) {
        float v0a, v0b, v1a, v1b;
        unpack2(acc[rp][0], v0a, v0b);
        unpack2(acc[rp][1], v1a, v1b);
        #pragma unroll
        for (int half = 0; half < 2; ++half) {
            int g = row0 + wr + 2 * rp + half;
            float v0 = half ? v0b : v0a;
            float v1 = half ? v1b : v1a;
            if (g < NN) {
                g_feat2[g * OUT_DIM + l] = v0;
                if (hi) g_feat2[g * OUT_DIM + 32 + l] = v1;
            }
            float p = v0 * a0 + v1 * a1;
            float q = v0 * r0 + v1 * r1;
            #pragma unroll
            for (int off = 16; off >= 1; off >>= 1) {
                p += __shfl_xor_sync(0xFFFFFFFFu, p, off);
                q += __shfl_xor_sync(0xFFFFFFFFu, q, off);
            }
            if (g < NN && l == 0) { g_el2[g] = p; g_er2[g] = q; }
        }
    }
}

// ------- layer-2 aggregation: warp/node, single pass, 4-edge unroll -------
__global__ __launch_bounds__(256) void agg2_kernel(const float* __restrict__ b2, float* __restrict__ out) {
    int n = (blockIdx.x * blockDim.x + threadIdx.x) >> 5;
    int l = threadIdx.x & 31;
    if (n >= NN) return;
    float er = g_er2[n];
    int s0 = g_rowptr[n], s1 = g_rowptr[n + 1];
    int lc = (l < 20) ? l : 19;

    const ull* f2 = (const ull*)g_feat2;
    ull aA = 0, aB = 0;
    float dsA = 0.f, dsB = 0.f;

    int i = s0;
    for (; i + 4 <= s1; i += 4) {
        int sa = g_esrc[i];
        int sb = g_esrc[i + 1];
        int sc = g_esrc[i + 2];
        int sd = g_esrc[i + 3];
        float ea = g_el2[sa] + er;
        float eb = g_el2[sb] + er;
        float ec = g_el2[sc] + er;
        float ed = g_el2[sd] + er;
        ull fa = f2[sa * 20 + lc];
        ull fb = f2[sb * 20 + lc];
        ull fc = f2[sc * 20 + lc];
        ull fd = f2[sd * 20 + lc];
        ea = fmaxf(ea, NEG_SLOPE * ea);
        eb = fmaxf(eb, NEG_SLOPE * eb);
        ec = fmaxf(ec, NEG_SLOPE * ec);
        ed = fmaxf(ed, NEG_SLOPE * ed);
        float wa = __expf(ea), wb = __expf(eb);
        float wc = __expf(ec), wd = __expf(ed);
        ffma2(aA, pack2(wa, wa), fa);
        ffma2(aB, pack2(wb, wb), fb);
        ffma2(aA, pack2(wc, wc), fc);
        ffma2(aB, pack2(wd, wd), fd);
        dsA += wa + wc; dsB += wb + wd;
    }
    for (; i < s1; ++i) {
        int sa = g_esrc[i];
        float ea = g_el2[sa] + er;
        ea = fmaxf(ea, NEG_SLOPE * ea);
        float wa = __expf(ea);
        ffma2(aA, pack2(wa, wa), f2[sa * 20 + lc]);
        dsA += wa;
    }

    if (l < 20) {
        float inv = 1.0f / fmaxf(dsA + dsB, 1e-9f);
        float xa, ya, xb, yb;
        unpack2(aA, xa, ya); unpack2(aB, xb, yb);
        float o0 = (xa + xb) * inv + b2[2 * l];
        float o1 = (ya + yb) * inv + b2[2 * l + 1];
        ((ull*)out)[n * 20 + l] = pack2(o0, o1);
    }
}

// ---------------- side stream for CSR/GEMM1 overlap ----------------
namespace {
struct Aux {
    cudaStream_t s2;
    cudaEvent_t fork, join;
    bool ok;
    Aux() : s2(nullptr), fork(nullptr), join(nullptr), ok(false) {
        if (cudaStreamCreateWithFlags(&s2, cudaStreamNonBlocking) != cudaSuccess) return;
        if (cudaEventCreateWithFlags(&fork, cudaEventDisableTiming) != cudaSuccess) return;
        if (cudaEventCreateWithFlags(&join, cudaEventDisableTiming) != cudaSuccess) return;
        ok = true;
    }
};
Aux g_aux;
}

// ---------------- launch ----------------
extern "C" void kernel_launch(void* const* d_in, const int* in_sizes, int n_in,
                              void* d_out, int out_size) {
    const float* h   = (const float*)d_in[0];
    const int*   src = (const int*)  d_in[1];
    const int*   dst = (const int*)  d_in[2];
    const float* W1  = (const float*)d_in[3];
    const float* al1 = (const float*)d_in[4];
    const float* ar1 = (const float*)d_in[5];
    const float* b1  = (const float*)d_in[6];
    const float* W2  = (const float*)d_in[7];
    const float* al2 = (const float*)d_in[8];
    const float* ar2 = (const float*)d_in[9];
    const float* b2  = (const float*)d_in[10];
    float* out = (float*)d_out;

    cudaFuncSetAttribute(gemm1_kernel, cudaFuncAttributeMaxDynamicSharedMemorySize, G1_SMEM);
    cudaFuncSetAttribute(gemm2_kernel, cudaFuncAttributeMaxDynamicSharedMemorySize, G2_SMEM);

    int nwarp_blocks = (NN * 32 + 255) / 256;
    int eblocks = (EE + 255) / 256;

    if (g_aux.ok) {
        // fork: CSR build on side stream; W1 convert + GEMM1 on main (gemm1 issued 4th).
        cudaEventRecord(g_aux.fork, 0);
        cudaStreamWaitEvent(g_aux.s2, g_aux.fork, 0);
        zero_kernel<<<(NN + 255) / 256, 256, 0, g_aux.s2>>>();            // 1
        hist_kernel<<<eblocks, 256, 0, g_aux.s2>>>(dst);                  // 2
        w1cvt_kernel<<<(IN_DIM * IN_DIM / 2 + 255) / 256, 256>>>(W1);     // 3 (main)
        gemm1_kernel<<<(NN + G1_ROWS - 1) / G1_ROWS, 256, G1_SMEM>>>(h, al1, ar1);  // 4 (main)
        scan1_kernel<<<NB, SCAN_B, 0, g_aux.s2>>>();                      // 5
        scan2_kernel<<<1, 128, 0, g_aux.s2>>>();                          // 6
        scan3_kernel<<<NB, SCAN_B, 0, g_aux.s2>>>();                      // 7
        scatter_kernel<<<eblocks, 256, 0, g_aux.s2>>>(src, dst);          // 8
        cudaEventRecord(g_aux.join, g_aux.s2);
        cudaStreamWaitEvent(0, g_aux.join, 0);
    } else {
        zero_kernel<<<(NN + 255) / 256, 256>>>();
        hist_kernel<<<eblocks, 256>>>(dst);
        w1cvt_kernel<<<(IN_DIM * IN_DIM / 2 + 255) / 256, 256>>>(W1);
        gemm1_kernel<<<(NN + G1_ROWS - 1) / G1_ROWS, 256, G1_SMEM>>>(h, al1, ar1);
        scan1_kernel<<<NB, SCAN_B>>>();
        scan2_kernel<<<1, 128>>>();
        scan3_kernel<<<NB, SCAN_B>>>();
        scatter_kernel<<<eblocks, 256>>>(src, dst);
    }

    agg1_kernel<<<nwarp_blocks, 256>>>(b1);
    gemm2_kernel<<<(NN + G2_ROWS - 1) / G2_ROWS, 256, G2_SMEM>>>(W2, al2, ar2);
    agg2_kernel<<<nwarp_blocks, 256>>>(b2, out);
}

// round 12
// speedup vs baseline: 1.5538x; 1.2323x over previous
#include <cuda_runtime.h>
#include <cuda_fp16.h>

#define NN 100000
#define EE 1600000
#define IN_DIM 128
#define HID 32
#define HEADS 4
#define OUT_DIM 40
#define NEG_SLOPE 0.2f

#define G1_ROWS 128
#define A_STRIDE 136                                  // fp16 elems, +8 pad
#define G1_SMEM ((G1_ROWS*A_STRIDE + IN_DIM*A_STRIDE) * 2)   // 69632 B
#define G2_ROWS 128
#define B2_STRIDE 48
#define G2_SMEM ((G2_ROWS*A_STRIDE + IN_DIM*B2_STRIDE) * 2)  // 47104 B
#define SCAN_B 1024
#define NB ((NN + SCAN_B - 1) / SCAN_B)   // 98

typedef unsigned long long ull;
typedef unsigned int uint;

// ---------------- f32x2 packed-math helpers (sm_103a) ----------------
__device__ __forceinline__ ull pack2(float a, float b) {
    ull r; asm("mov.b64 %0,{%1,%2};" : "=l"(r) : "f"(a), "f"(b)); return r;
}
__device__ __forceinline__ void unpack2(ull p, float& a, float& b) {
    asm("mov.b64 {%0,%1},%2;" : "=f"(a), "=f"(b) : "l"(p));
}
__device__ __forceinline__ void ffma2(ull& acc, ull a, ull b) {
    asm("fma.rn.f32x2 %0,%1,%2,%0;" : "+l"(acc) : "l"(a), "l"(b));
}

// ---------------- scratch (device globals: allocation-free) ----------------
__device__ float  g_feat1[NN * IN_DIM];
__device__ float  g_el1[NN * HEADS];
__device__ float  g_er1[NN * HEADS];
__device__ __half g_h1h[NN * IN_DIM];      // layer-2 input, fp16 (only gemm2 reads it)
__device__ float  g_feat2[NN * OUT_DIM];
__device__ float  g_el2[NN];
__device__ float  g_er2[NN];
__device__ __half g_W1h[IN_DIM * IN_DIM];
__device__ int    g_deg[NN];
__device__ int    g_rank[EE];
__device__ int    g_rowptr[NN + 1];
__device__ int    g_esrc[EE];
__device__ int    g_bsum[128];
__device__ int    g_boff[128];

// ---------------- zero deg ----------------
__global__ void zero_kernel() {
    int i = blockIdx.x * blockDim.x + threadIdx.x;
    if (i < NN) g_deg[i] = 0;
}

// ---------------- W1 fp32 -> fp16 (once per launch) ----------------
__global__ void w1cvt_kernel(const float* __restrict__ W1) {
    int i = blockIdx.x * blockDim.x + threadIdx.x;
    if (i < IN_DIM * IN_DIM / 2) {
        float2 f = ((const float2*)W1)[i];
        ((__half2*)g_W1h)[i] = __floats2half2_rn(f.x, f.y);
    }
}

// ---- GEMM1 on tensor cores: 128-row tile, 512 thr, fused el1/er1 ----
__global__ __launch_bounds__(512) void gemm1_kernel(const float* __restrict__ h,
                                                    const float* __restrict__ al1,
                                                    const float* __restrict__ ar1) {
    extern __shared__ __half smh[];
    __half* As = smh;                          // [128][A_STRIDE]
    __half* Ws = smh + G1_ROWS * A_STRIDE;     // [128][A_STRIDE]
    int t = threadIdx.x;
    int row0 = blockIdx.x * G1_ROWS;

    for (int i = t; i < IN_DIM * IN_DIM / 8; i += 512) {
        int r = i >> 4, c8 = i & 15;
        uint4 v = ((const uint4*)g_W1h)[i];
        *(uint4*)(Ws + r * A_STRIDE + c8 * 8) = v;
    }
    const float4* H4 = (const float4*)h;
    for (int i = t; i < G1_ROWS * IN_DIM / 4; i += 512) {
        int r = i >> 5, c4 = i & 31;
        int g = row0 + r;
        float4 f = (g < NN) ? H4[g * 32 + c4] : make_float4(0.f, 0.f, 0.f, 0.f);
        __half2 lo = __floats2half2_rn(f.x, f.y);
        __half2 hi = __floats2half2_rn(f.z, f.w);
        uint2 v;
        v.x = *(uint*)&lo; v.y = *(uint*)&hi;
        *(uint2*)(As + r * A_STRIDE + c4 * 4) = v;
    }
    __syncthreads();

    int w = t >> 5, lane = t & 31;
    int rw = (w & 7) * 16;          // warp's 16 rows
    int ch = (w >> 3) * 64;         // warp's 64-col half

    uint a_base = (uint)__cvta_generic_to_shared(
        As + (rw + (lane & 15)) * A_STRIDE + ((lane >> 4) * 8));
    uint b_base = (uint)__cvta_generic_to_shared(
        Ws + (lane & 15) * A_STRIDE + ch + ((lane >> 4) * 8));

    float acc[8][4];
    #pragma unroll
    for (int j = 0; j < 8; ++j)
        #pragma unroll
        for (int c = 0; c < 4; ++c) acc[j][c] = 0.f;

    #pragma unroll
    for (int kb = 0; kb < 8; ++kb) {
        uint a0, a1, a2, a3;
        asm volatile("ldmatrix.sync.aligned.m8n8.x4.shared.b16 {%0,%1,%2,%3}, [%4];"
                     : "=r"(a0), "=r"(a1), "=r"(a2), "=r"(a3)
                     : "r"(a_base + kb * 32));
        #pragma unroll
        for (int p = 0; p < 4; ++p) {
            uint b0, b1, b2, b3;
            asm volatile("ldmatrix.sync.aligned.m8n8.x4.trans.shared.b16 {%0,%1,%2,%3}, [%4];"
                         : "=r"(b0), "=r"(b1), "=r"(b2), "=r"(b3)
                         : "r"(b_base + kb * 16 * A_STRIDE * 2 + p * 32));
            asm volatile("mma.sync.aligned.m16n8k16.row.col.f32.f16.f16.f32 "
                         "{%0,%1,%2,%3}, {%4,%5,%6,%7}, {%8,%9}, {%0,%1,%2,%3};"
                         : "+f"(acc[2*p][0]), "+f"(acc[2*p][1]), "+f"(acc[2*p][2]), "+f"(acc[2*p][3])
                         : "r"(a0), "r"(a1), "r"(a2), "r"(a3), "r"(b0), "r"(b1));
            asm volatile("mma.sync.aligned.m16n8k16.row.col.f32.f16.f16.f32 "
                         "{%0,%1,%2,%3}, {%4,%5,%6,%7}, {%8,%9}, {%0,%1,%2,%3};"
                         : "+f"(acc[2*p+1][0]), "+f"(acc[2*p+1][1]), "+f"(acc[2*p+1][2]), "+f"(acc[2*p+1][3])
                         : "r"(a0), "r"(a1), "r"(a2), "r"(a3), "r"(b2), "r"(b3));
        }
    }

    int g0 = lane >> 2, quad = lane & 3;
    int r0g = row0 + rw + g0;
    int r1g = r0g + 8;
    int h0 = (w >> 3) * 2;

    float pe[2][2] = {{0.f, 0.f}, {0.f, 0.f}};
    float pr[2][2] = {{0.f, 0.f}, {0.f, 0.f}};

    #pragma unroll
    for (int j = 0; j < 8; ++j) {
        int n0 = ch + j * 8 + quad * 2;
        float2 av = *(const float2*)(al1 + n0);
        float2 rv = *(const float2*)(ar1 + n0);
        if (r0g < NN) *(float2*)(g_feat1 + r0g * IN_DIM + n0) = make_float2(acc[j][0], acc[j][1]);
        if (r1g < NN) *(float2*)(g_feat1 + r1g * IN_DIM + n0) = make_float2(acc[j][2], acc[j][3]);
        int hi = j >> 2;
        pe[hi][0] += acc[j][0] * av.x + acc[j][1] * av.y;
        pe[hi][1] += acc[j][2] * av.x + acc[j][3] * av.y;
        pr[hi][0] += acc[j][0] * rv.x + acc[j][1] * rv.y;
        pr[hi][1] += acc[j][2] * rv.x + acc[j][3] * rv.y;
    }
    #pragma unroll
    for (int hi = 0; hi < 2; ++hi)
        #pragma unroll
        for (int rr = 0; rr < 2; ++rr) {
            float e = pe[hi][rr], r = pr[hi][rr];
            e += __shfl_xor_sync(0xFFFFFFFFu, e, 1);
            e += __shfl_xor_sync(0xFFFFFFFFu, e, 2);
            r += __shfl_xor_sync(0xFFFFFFFFu, r, 1);
            r += __shfl_xor_sync(0xFFFFFFFFu, r, 2);
            int g = rr ? r1g : r0g;
            if (quad == 0 && g < NN) {
                g_el1[g * 4 + h0 + hi] = e;
                g_er1[g * 4 + h0 + hi] = r;
            }
        }
}

// ---------------- CSR build ----------------
__global__ void hist_kernel(const int* __restrict__ dst) {
    int i = blockIdx.x * blockDim.x + threadIdx.x;
    if (i < EE) g_rank[i] = atomicAdd(&g_deg[dst[i]], 1);
}

__global__ void scan1_kernel() {
    __shared__ int ws[32];
    int t = threadIdx.x;
    int lane = t & 31, wp = t >> 5;
    int i = blockIdx.x * SCAN_B + t;
    int v = (i < NN) ? g_deg[i] : 0;
    int x = v;
    #pragma unroll
    for (int off = 1; off < 32; off <<= 1) {
        int y = __shfl_up_sync(0xFFFFFFFFu, x, off);
        if (lane >= off) x += y;
    }
    if (lane == 31) ws[wp] = x;
    __syncthreads();
    if (wp == 0) {
        int o = ws[lane];
        int s = o;
        #pragma unroll
        for (int off = 1; off < 32; off <<= 1) {
            int y = __shfl_up_sync(0xFFFFFFFFu, s, off);
            if (lane >= off) s += y;
        }
        ws[lane] = s - o;
    }
    __syncthreads();
    int base = ws[wp];
    if (i < NN) g_rowptr[i] = x - v + base;
    if (t == SCAN_B - 1) g_bsum[blockIdx.x] = x + base;
}

__global__ void scan2_kernel() {
    int t = threadIdx.x;
    int lane = t & 31, wp = t >> 5;
    int v = (t < NB) ? g_bsum[t] : 0;
    int x = v;
    #pragma unroll
    for (int off = 1; off < 32; off <<= 1) {
        int y = __shfl_up_sync(0xFFFFFFFFu, x, off);
        if (lane >= off) x += y;
    }
    __shared__ int wsum[4];
    if (lane == 31) wsum[wp] = x;
    __syncthreads();
    int add = 0;
    for (int w = 0; w < wp; ++w) add += wsum[w];
    if (t < NB) g_boff[t] = x - v + add;
}

__global__ void scan3_kernel() {
    int i = blockIdx.x * SCAN_B + threadIdx.x;
    if (i < NN) g_rowptr[i] += g_boff[blockIdx.x];
    if (i == 0) g_rowptr[NN] = EE;
}

__global__ void scatter_kernel(const int* __restrict__ src, const int* __restrict__ dst) {
    int i = blockIdx.x * blockDim.x + threadIdx.x;
    if (i < EE) {
        int d = dst[i];
        g_esrc[g_rowptr[d] + g_rank[i]] = src[i];
    }
}

// ------- layer-1 aggregation: warp/node, 4-edge unroll, fp16 h1 out -------
__global__ __launch_bounds__(256) void agg1_kernel(const float* __restrict__ b1) {
    int n = (blockIdx.x * blockDim.x + threadIdx.x) >> 5;
    int l = threadIdx.x & 31;
    if (n >= NN) return;
    int hh = l >> 3;
    float erh = g_er1[n * 4 + hh];
    int s0 = g_rowptr[n], s1 = g_rowptr[n + 1];

    const ulonglong2* f2 = (const ulonglong2*)g_feat1;
    ull aA0 = 0, aA1 = 0, aB0 = 0, aB1 = 0;
    float dsA = 0.f, dsB = 0.f;

    int i = s0;
    for (; i + 4 <= s1; i += 4) {
        int sa = g_esrc[i];
        int sb = g_esrc[i + 1];
        int sc = g_esrc[i + 2];
        int sd = g_esrc[i + 3];
        float ea = g_el1[sa * 4 + hh] + erh;
        float eb = g_el1[sb * 4 + hh] + erh;
        float ec = g_el1[sc * 4 + hh] + erh;
        float ed = g_el1[sd * 4 + hh] + erh;
        ulonglong2 fa = f2[sa * 32 + l];
        ulonglong2 fb = f2[sb * 32 + l];
        ulonglong2 fc = f2[sc * 32 + l];
        ulonglong2 fd = f2[sd * 32 + l];
        ea = fmaxf(ea, NEG_SLOPE * ea);
        eb = fmaxf(eb, NEG_SLOPE * eb);
        ec = fmaxf(ec, NEG_SLOPE * ec);
        ed = fmaxf(ed, NEG_SLOPE * ed);
        float wa = __expf(ea), wb = __expf(eb);
        float wc = __expf(ec), wd = __expf(ed);
        ull wa2 = pack2(wa, wa), wb2 = pack2(wb, wb);
        ull wc2 = pack2(wc, wc), wd2 = pack2(wd, wd);
        ffma2(aA0, wa2, fa.x); ffma2(aA1, wa2, fa.y);
        ffma2(aB0, wb2, fb.x); ffma2(aB1, wb2, fb.y);
        ffma2(aA0, wc2, fc.x); ffma2(aA1, wc2, fc.y);
        ffma2(aB0, wd2, fd.x); ffma2(aB1, wd2, fd.y);
        dsA += wa + wc; dsB += wb + wd;
    }
    for (; i < s1; ++i) {
        int sa = g_esrc[i];
        float ea = g_el1[sa * 4 + hh] + erh;
        ea = fmaxf(ea, NEG_SLOPE * ea);
        float wa = __expf(ea);
        ulonglong2 fa = f2[sa * 32 + l];
        ull wa2 = pack2(wa, wa);
        ffma2(aA0, wa2, fa.x); ffma2(aA1, wa2, fa.y);
        dsA += wa;
    }

    float inv = 1.0f / fmaxf(dsA + dsB, 1e-9f);
    float xA, yA, xB, yB, zA, wA, zB, wB;
    unpack2(aA0, xA, yA); unpack2(aB0, xB, yB);
    unpack2(aA1, zA, wA); unpack2(aB1, zB, wB);
    float4 bb = ((const float4*)b1)[l];
    float o0 = fmaxf((xA + xB) * inv + bb.x, 0.f);
    float o1 = fmaxf((yA + yB) * inv + bb.y, 0.f);
    float o2 = fmaxf((zA + zB) * inv + bb.z, 0.f);
    float o3 = fmaxf((wA + wB) * inv + bb.w, 0.f);
    __half2 lo = __floats2half2_rn(o0, o1);
    __half2 hi = __floats2half2_rn(o2, o3);
    uint2 v;
    v.x = *(uint*)&lo; v.y = *(uint*)&hi;
    ((uint2*)g_h1h)[n * 32 + l] = v;
}

// ------- GEMM2 on tensor cores: 128-row tile, fused el2/er2 -------
__global__ __launch_bounds__(256) void gemm2_kernel(const float* __restrict__ W2,
                                                    const float* __restrict__ al2,
                                                    const float* __restrict__ ar2) {
    extern __shared__ __half smh[];
    __half* As = smh;                          // [128][A_STRIDE]
    __half* Bs = smh + G2_ROWS * A_STRIDE;     // [128][B2_STRIDE], cols 40-47 zero
    int t = threadIdx.x;
    int row0 = blockIdx.x * G2_ROWS;

    // A: h1 fp16 tile
    for (int i = t; i < G2_ROWS * IN_DIM / 8; i += 256) {
        int r = i >> 4, c8 = i & 15;
        int g = row0 + r;
        uint4 v = (g < NN) ? ((const uint4*)g_h1h)[g * 16 + c8]
                           : make_uint4(0u, 0u, 0u, 0u);
        *(uint4*)(As + r * A_STRIDE + c8 * 8) = v;
    }
    // B: W2 fp32 -> fp16, pad cols 40-47 with zeros
    for (int i = t; i < IN_DIM * OUT_DIM; i += 256) {
        int r = i / OUT_DIM, c = i - r * OUT_DIM;
        Bs[r * B2_STRIDE + c] = __float2half_rn(W2[i]);
    }
    for (int i = t; i < IN_DIM * 8; i += 256) {
        int r = i >> 3, c = i & 7;
        Bs[r * B2_STRIDE + OUT_DIM + c] = __float2half_rn(0.f);
    }
    __syncthreads();

    int w = t >> 5, lane = t & 31;
    int rw = w * 16;     // 8 warps x 16 rows = 128

    uint a_base = (uint)__cvta_generic_to_shared(
        As + (rw + (lane & 15)) * A_STRIDE + ((lane >> 4) * 8));
    uint b_base = (uint)__cvta_generic_to_shared(
        Bs + (lane & 15) * B2_STRIDE + ((lane >> 4) * 8));

    float acc[6][4];
    #pragma unroll
    for (int j = 0; j < 6; ++j)
        #pragma unroll
        for (int c = 0; c < 4; ++c) acc[j][c] = 0.f;

    #pragma unroll
    for (int kb = 0; kb < 8; ++kb) {
        uint a0, a1, a2, a3;
        asm volatile("ldmatrix.sync.aligned.m8n8.x4.shared.b16 {%0,%1,%2,%3}, [%4];"
                     : "=r"(a0), "=r"(a1), "=r"(a2), "=r"(a3)
                     : "r"(a_base + kb * 32));
        #pragma unroll
        for (int p = 0; p < 3; ++p) {
            uint b0, b1, b2, b3;
            asm volatile("ldmatrix.sync.aligned.m8n8.x4.trans.shared.b16 {%0,%1,%2,%3}, [%4];"
                         : "=r"(b0), "=r"(b1), "=r"(b2), "=r"(b3)
                         : "r"(b_base + kb * 16 * B2_STRIDE * 2 + p * 32));
            asm volatile("mma.sync.aligned.m16n8k16.row.col.f32.f16.f16.f32 "
                         "{%0,%1,%2,%3}, {%4,%5,%6,%7}, {%8,%9}, {%0,%1,%2,%3};"
                         : "+f"(acc[2*p][0]), "+f"(acc[2*p][1]), "+f"(acc[2*p][2]), "+f"(acc[2*p][3])
                         : "r"(a0), "r"(a1), "r"(a2), "r"(a3), "r"(b0), "r"(b1));
            asm volatile("mma.sync.aligned.m16n8k16.row.col.f32.f16.f16.f32 "
                         "{%0,%1,%2,%3}, {%4,%5,%6,%7}, {%8,%9}, {%0,%1,%2,%3};"
                         : "+f"(acc[2*p+1][0]), "+f"(acc[2*p+1][1]), "+f"(acc[2*p+1][2]), "+f"(acc[2*p+1][3])
                         : "r"(a0), "r"(a1), "r"(a2), "r"(a3), "r"(b2), "r"(b3));
        }
    }

    int g0 = lane >> 2, quad = lane & 3;
    int r0g = row0 + rw + g0;
    int r1g = r0g + 8;

    float p0 = 0.f, p1 = 0.f, q0 = 0.f, q1 = 0.f;
    #pragma unroll
    for (int j = 0; j < 5; ++j) {
        int n0 = j * 8 + quad * 2;
        float2 av = *(const float2*)(al2 + n0);
        float2 rv = *(const float2*)(ar2 + n0);
        if (r0g < NN) *(float2*)(g_feat2 + r0g * OUT_DIM + n0) = make_float2(acc[j][0], acc[j][1]);
        if (r1g < NN) *(float2*)(g_feat2 + r1g * OUT_DIM + n0) = make_float2(acc[j][2], acc[j][3]);
        p0 += acc[j][0] * av.x + acc[j][1] * av.y;
        p1 += acc[j][2] * av.x + acc[j][3] * av.y;
        q0 += acc[j][0] * rv.x + acc[j][1] * rv.y;
        q1 += acc[j][2] * rv.x + acc[j][3] * rv.y;
    }
    #pragma unroll
    for (int off = 1; off <= 2; off <<= 1) {
        p0 += __shfl_xor_sync(0xFFFFFFFFu, p0, off);
        p1 += __shfl_xor_sync(0xFFFFFFFFu, p1, off);
        q0 += __shfl_xor_sync(0xFFFFFFFFu, q0, off);
        q1 += __shfl_xor_sync(0xFFFFFFFFu, q1, off);
    }
    if (quad == 0) {
        if (r0g < NN) { g_el2[r0g] = p0; g_er2[r0g] = q0; }
        if (r1g < NN) { g_el2[r1g] = p1; g_er2[r1g] = q1; }
    }
}

// ------- layer-2 aggregation: warp/node, single pass, 4-edge unroll -------
__global__ __launch_bounds__(256) void agg2_kernel(const float* __restrict__ b2, float* __restrict__ out) {
    int n = (blockIdx.x * blockDim.x + threadIdx.x) >> 5;
    int l = threadIdx.x & 31;
    if (n >= NN) return;
    float er = g_er2[n];
    int s0 = g_rowptr[n], s1 = g_rowptr[n + 1];
    int lc = (l < 20) ? l : 19;

    const ull* f2 = (const ull*)g_feat2;
    ull aA = 0, aB = 0;
    float dsA = 0.f, dsB = 0.f;

    int i = s0;
    for (; i + 4 <= s1; i += 4) {
        int sa = g_esrc[i];
        int sb = g_esrc[i + 1];
        int sc = g_esrc[i + 2];
        int sd = g_esrc[i + 3];
        float ea = g_el2[sa] + er;
        float eb = g_el2[sb] + er;
        float ec = g_el2[sc] + er;
        float ed = g_el2[sd] + er;
        ull fa = f2[sa * 20 + lc];
        ull fb = f2[sb * 20 + lc];
        ull fc = f2[sc * 20 + lc];
        ull fd = f2[sd * 20 + lc];
        ea = fmaxf(ea, NEG_SLOPE * ea);
        eb = fmaxf(eb, NEG_SLOPE * eb);
        ec = fmaxf(ec, NEG_SLOPE * ec);
        ed = fmaxf(ed, NEG_SLOPE * ed);
        float wa = __expf(ea), wb = __expf(eb);
        float wc = __expf(ec), wd = __expf(ed);
        ffma2(aA, pack2(wa, wa), fa);
        ffma2(aB, pack2(wb, wb), fb);
        ffma2(aA, pack2(wc, wc), fc);
        ffma2(aB, pack2(wd, wd), fd);
        dsA += wa + wc; dsB += wb + wd;
    }
    for (; i < s1; ++i) {
        int sa = g_esrc[i];
        float ea = g_el2[sa] + er;
        ea = fmaxf(ea, NEG_SLOPE * ea);
        float wa = __expf(ea);
        ffma2(aA, pack2(wa, wa), f2[sa * 20 + lc]);
        dsA += wa;
    }

    if (l < 20) {
        float inv = 1.0f / fmaxf(dsA + dsB, 1e-9f);
        float xa, ya, xb, yb;
        unpack2(aA, xa, ya); unpack2(aB, xb, yb);
        float o0 = (xa + xb) * inv + b2[2 * l];
        float o1 = (ya + yb) * inv + b2[2 * l + 1];
        ((ull*)out)[n * 20 + l] = pack2(o0, o1);
    }
}

// ---------------- side stream for CSR/GEMM1 overlap ----------------
namespace {
struct Aux {
    cudaStream_t s2;
    cudaEvent_t fork, join;
    bool ok;
    Aux() : s2(nullptr), fork(nullptr), join(nullptr), ok(false) {
        if (cudaStreamCreateWithFlags(&s2, cudaStreamNonBlocking) != cudaSuccess) return;
        if (cudaEventCreateWithFlags(&fork, cudaEventDisableTiming) != cudaSuccess) return;
        if (cudaEventCreateWithFlags(&join, cudaEventDisableTiming) != cudaSuccess) return;
        ok = true;
    }
};
Aux g_aux;
}

// ---------------- launch ----------------
extern "C" void kernel_launch(void* const* d_in, const int* in_sizes, int n_in,
                              void* d_out, int out_size) {
    const float* h   = (const float*)d_in[0];
    const int*   src = (const int*)  d_in[1];
    const int*   dst = (const int*)  d_in[2];
    const float* W1  = (const float*)d_in[3];
    const float* al1 = (const float*)d_in[4];
    const float* ar1 = (const float*)d_in[5];
    const float* b1  = (const float*)d_in[6];
    const float* W2  = (const float*)d_in[7];
    const float* al2 = (const float*)d_in[8];
    const float* ar2 = (const float*)d_in[9];
    const float* b2  = (const float*)d_in[10];
    float* out = (float*)d_out;

    cudaFuncSetAttribute(gemm1_kernel, cudaFuncAttributeMaxDynamicSharedMemorySize, G1_SMEM);
    cudaFuncSetAttribute(gemm2_kernel, cudaFuncAttributeMaxDynamicSharedMemorySize, G2_SMEM);

    int nwarp_blocks = (NN * 32 + 255) / 256;
    int eblocks = (EE + 255) / 256;
    int g1blocks = (NN + G1_ROWS - 1) / G1_ROWS;
    int g2blocks = (NN + G2_ROWS - 1) / G2_ROWS;

    if (g_aux.ok) {
        cudaEventRecord(g_aux.fork, 0);
        cudaStreamWaitEvent(g_aux.s2, g_aux.fork, 0);
        zero_kernel<<<(NN + 255) / 256, 256, 0, g_aux.s2>>>();            // 1
        hist_kernel<<<eblocks, 256, 0, g_aux.s2>>>(dst);                  // 2
        w1cvt_kernel<<<(IN_DIM * IN_DIM / 2 + 255) / 256, 256>>>(W1);     // 3 (main)
        gemm1_kernel<<<g1blocks, 512, G1_SMEM>>>(h, al1, ar1);            // 4 (main, profiled)
        scan1_kernel<<<NB, SCAN_B, 0, g_aux.s2>>>();                      // 5
        scan2_kernel<<<1, 128, 0, g_aux.s2>>>();                          // 6
        scan3_kernel<<<NB, SCAN_B, 0, g_aux.s2>>>();                      // 7
        scatter_kernel<<<eblocks, 256, 0, g_aux.s2>>>(src, dst);          // 8
        cudaEventRecord(g_aux.join, g_aux.s2);
        cudaStreamWaitEvent(0, g_aux.join, 0);
    } else {
        zero_kernel<<<(NN + 255) / 256, 256>>>();
        hist_kernel<<<eblocks, 256>>>(dst);
        w1cvt_kernel<<<(IN_DIM * IN_DIM / 2 + 255) / 256, 256>>>(W1);
        gemm1_kernel<<<g1blocks, 512, G1_SMEM>>>(h, al1, ar1);
        scan1_kernel<<<NB, SCAN_B>>>();
        scan2_kernel<<<1, 128>>>();
        scan3_kernel<<<NB, SCAN_B>>>();
        scatter_kernel<<<eblocks, 256>>>(src, dst);
    }

    agg1_kernel<<<nwarp_blocks, 256>>>(b1);
    gemm2_kernel<<<g2blocks, 256, G2_SMEM>>>(W2, al2, ar2);
    agg2_kernel<<<nwarp_blocks, 256>>>(b2, out);
}

// round 13
// speedup vs baseline: 1.6182x; 1.0415x over previous
#include <cuda_runtime.h>
#include <cuda_fp16.h>
#include <string.h>

#define NN 100000
#define EE 1600000
#define IN_DIM 128
#define HID 32
#define HEADS 4
#define OUT_DIM 40
#define NEG_SLOPE 0.2f

#define G1_ROWS 128
#define A_STRIDE 136                                  // fp16 elems, +8 pad
#define G1_SMEM ((G1_ROWS*A_STRIDE + IN_DIM*A_STRIDE) * 2)   // 69632 B
#define G2_ROWS 128
#define B2_STRIDE 48
#define G2_SMEM ((G2_ROWS*A_STRIDE + IN_DIM*B2_STRIDE) * 2)  // 47104 B
#define SCAN_B 1024
#define NB ((NN + SCAN_B - 1) / SCAN_B)   // 98

typedef unsigned long long ull;
typedef unsigned int uint;

// ---------------- f32x2 packed-math helpers (sm_103a) ----------------
__device__ __forceinline__ ull pack2(float a, float b) {
    ull r; asm("mov.b64 %0,{%1,%2};" : "=l"(r) : "f"(a), "f"(b)); return r;
}
__device__ __forceinline__ void unpack2(ull p, float& a, float& b) {
    asm("mov.b64 {%0,%1},%2;" : "=f"(a), "=f"(b) : "l"(p));
}
__device__ __forceinline__ void ffma2(ull& acc, ull a, ull b) {
    asm("fma.rn.f32x2 %0,%1,%2,%0;" : "+l"(acc) : "l"(a), "l"(b));
}
// ---------------- fp16 bit-cast helpers ----------------
__device__ __forceinline__ uint f2_to_h2u(float a, float b) {
    __half2 h = __floats2half2_rn(a, b);
    uint u; memcpy(&u, &h, 4); return u;
}
__device__ __forceinline__ float2 h2u_to_f2(uint u) {
    __half2 h; memcpy(&h, &u, 4);
    return __half22float2(h);
}

// ---------------- scratch (device globals: allocation-free) ----------------
__device__ __half g_feat1h[NN * IN_DIM];   // fp16: gemm1 out -> agg1 gather
__device__ float  g_el1[NN * HEADS];
__device__ float  g_er1[NN * HEADS];
__device__ __half g_h1h[NN * IN_DIM];      // fp16: agg1 out -> gemm2 in
__device__ __half g_feat2h[NN * OUT_DIM];  // fp16: gemm2 out -> agg2 gather
__device__ float  g_el2[NN];
__device__ float  g_er2[NN];
__device__ __half g_W1h[IN_DIM * IN_DIM];
__device__ int    g_deg[NN];
__device__ int    g_rank[EE];
__device__ int    g_rowptr[NN + 1];
__device__ int    g_esrc[EE];
__device__ int    g_bsum[128];
__device__ int    g_boff[128];

// ---------------- zero deg ----------------
__global__ void zero_kernel() {
    int i = blockIdx.x * blockDim.x + threadIdx.x;
    if (i < NN) g_deg[i] = 0;
}

// ---------------- W1 fp32 -> fp16 (once per launch) ----------------
__global__ void w1cvt_kernel(const float* __restrict__ W1) {
    int i = blockIdx.x * blockDim.x + threadIdx.x;
    if (i < IN_DIM * IN_DIM / 2) {
        float2 f = ((const float2*)W1)[i];
        ((__half2*)g_W1h)[i] = __floats2half2_rn(f.x, f.y);
    }
}

// ---- GEMM1 on tensor cores: 128-row tile, 512 thr, fused el1/er1, fp16 out ----
__global__ __launch_bounds__(512) void gemm1_kernel(const float* __restrict__ h,
                                                    const float* __restrict__ al1,
                                                    const float* __restrict__ ar1) {
    extern __shared__ __half smh[];
    __half* As = smh;                          // [128][A_STRIDE]
    __half* Ws = smh + G1_ROWS * A_STRIDE;     // [128][A_STRIDE]
    int t = threadIdx.x;
    int row0 = blockIdx.x * G1_ROWS;

    for (int i = t; i < IN_DIM * IN_DIM / 8; i += 512) {
        int r = i >> 4, c8 = i & 15;
        uint4 v = ((const uint4*)g_W1h)[i];
        *(uint4*)(Ws + r * A_STRIDE + c8 * 8) = v;
    }
    const float4* H4 = (const float4*)h;
    for (int i = t; i < G1_ROWS * IN_DIM / 4; i += 512) {
        int r = i >> 5, c4 = i & 31;
        int g = row0 + r;
        float4 f = (g < NN) ? H4[g * 32 + c4] : make_float4(0.f, 0.f, 0.f, 0.f);
        uint2 v;
        v.x = f2_to_h2u(f.x, f.y);
        v.y = f2_to_h2u(f.z, f.w);
        *(uint2*)(As + r * A_STRIDE + c4 * 4) = v;
    }
    __syncthreads();

    int w = t >> 5, lane = t & 31;
    int rw = (w & 7) * 16;          // warp's 16 rows
    int ch = (w >> 3) * 64;         // warp's 64-col half

    uint a_base = (uint)__cvta_generic_to_shared(
        As + (rw + (lane & 15)) * A_STRIDE + ((lane >> 4) * 8));
    uint b_base = (uint)__cvta_generic_to_shared(
        Ws + (lane & 15) * A_STRIDE + ch + ((lane >> 4) * 8));

    float acc[8][4];
    #pragma unroll
    for (int j = 0; j < 8; ++j)
        #pragma unroll
        for (int c = 0; c < 4; ++c) acc[j][c] = 0.f;

    #pragma unroll
    for (int kb = 0; kb < 8; ++kb) {
        uint a0, a1, a2, a3;
        asm volatile("ldmatrix.sync.aligned.m8n8.x4.shared.b16 {%0,%1,%2,%3}, [%4];"
                     : "=r"(a0), "=r"(a1), "=r"(a2), "=r"(a3)
                     : "r"(a_base + kb * 32));
        #pragma unroll
        for (int p = 0; p < 4; ++p) {
            uint b0, b1, b2, b3;
            asm volatile("ldmatrix.sync.aligned.m8n8.x4.trans.shared.b16 {%0,%1,%2,%3}, [%4];"
                         : "=r"(b0), "=r"(b1), "=r"(b2), "=r"(b3)
                         : "r"(b_base + kb * 16 * A_STRIDE * 2 + p * 32));
            asm volatile("mma.sync.aligned.m16n8k16.row.col.f32.f16.f16.f32 "
                         "{%0,%1,%2,%3}, {%4,%5,%6,%7}, {%8,%9}, {%0,%1,%2,%3};"
                         : "+f"(acc[2*p][0]), "+f"(acc[2*p][1]), "+f"(acc[2*p][2]), "+f"(acc[2*p][3])
                         : "r"(a0), "r"(a1), "r"(a2), "r"(a3), "r"(b0), "r"(b1));
            asm volatile("mma.sync.aligned.m16n8k16.row.col.f32.f16.f16.f32 "
                         "{%0,%1,%2,%3}, {%4,%5,%6,%7}, {%8,%9}, {%0,%1,%2,%3};"
                         : "+f"(acc[2*p+1][0]), "+f"(acc[2*p+1][1]), "+f"(acc[2*p+1][2]), "+f"(acc[2*p+1][3])
                         : "r"(a0), "r"(a1), "r"(a2), "r"(a3), "r"(b2), "r"(b3));
        }
    }

    int g0 = lane >> 2, quad = lane & 3;
    int r0g = row0 + rw + g0;
    int r1g = r0g + 8;
    int h0 = (w >> 3) * 2;

    float pe[2][2] = {{0.f, 0.f}, {0.f, 0.f}};
    float pr[2][2] = {{0.f, 0.f}, {0.f, 0.f}};

    #pragma unroll
    for (int j = 0; j < 8; ++j) {
        int n0 = ch + j * 8 + quad * 2;
        float2 av = *(const float2*)(al1 + n0);
        float2 rv = *(const float2*)(ar1 + n0);
        if (r0g < NN) ((uint*)g_feat1h)[(r0g * IN_DIM + n0) >> 1] = f2_to_h2u(acc[j][0], acc[j][1]);
        if (r1g < NN) ((uint*)g_feat1h)[(r1g * IN_DIM + n0) >> 1] = f2_to_h2u(acc[j][2], acc[j][3]);
        int hi = j >> 2;
        pe[hi][0] += acc[j][0] * av.x + acc[j][1] * av.y;
        pe[hi][1] += acc[j][2] * av.x + acc[j][3] * av.y;
        pr[hi][0] += acc[j][0] * rv.x + acc[j][1] * rv.y;
        pr[hi][1] += acc[j][2] * rv.x + acc[j][3] * rv.y;
    }
    #pragma unroll
    for (int hi = 0; hi < 2; ++hi)
        #pragma unroll
        for (int rr = 0; rr < 2; ++rr) {
            float e = pe[hi][rr], r = pr[hi][rr];
            e += __shfl_xor_sync(0xFFFFFFFFu, e, 1);
            e += __shfl_xor_sync(0xFFFFFFFFu, e, 2);
            r += __shfl_xor_sync(0xFFFFFFFFu, r, 1);
            r += __shfl_xor_sync(0xFFFFFFFFu, r, 2);
            int g = rr ? r1g : r0g;
            if (quad == 0 && g < NN) {
                g_el1[g * 4 + h0 + hi] = e;
                g_er1[g * 4 + h0 + hi] = r;
            }
        }
}

// ---------------- CSR build ----------------
__global__ void hist_kernel(const int* __restrict__ dst) {
    int i = blockIdx.x * blockDim.x + threadIdx.x;
    if (i < EE) g_rank[i] = atomicAdd(&g_deg[dst[i]], 1);
}

__global__ void scan1_kernel() {
    __shared__ int ws[32];
    int t = threadIdx.x;
    int lane = t & 31, wp = t >> 5;
    int i = blockIdx.x * SCAN_B + t;
    int v = (i < NN) ? g_deg[i] : 0;
    int x = v;
    #pragma unroll
    for (int off = 1; off < 32; off <<= 1) {
        int y = __shfl_up_sync(0xFFFFFFFFu, x, off);
        if (lane >= off) x += y;
    }
    if (lane == 31) ws[wp] = x;
    __syncthreads();
    if (wp == 0) {
        int o = ws[lane];
        int s = o;
        #pragma unroll
        for (int off = 1; off < 32; off <<= 1) {
            int y = __shfl_up_sync(0xFFFFFFFFu, s, off);
            if (lane >= off) s += y;
        }
        ws[lane] = s - o;
    }
    __syncthreads();
    int base = ws[wp];
    if (i < NN) g_rowptr[i] = x - v + base;
    if (t == SCAN_B - 1) g_bsum[blockIdx.x] = x + base;
}

__global__ void scan2_kernel() {
    int t = threadIdx.x;
    int lane = t & 31, wp = t >> 5;
    int v = (t < NB) ? g_bsum[t] : 0;
    int x = v;
    #pragma unroll
    for (int off = 1; off < 32; off <<= 1) {
        int y = __shfl_up_sync(0xFFFFFFFFu, x, off);
        if (lane >= off) x += y;
    }
    __shared__ int wsum[4];
    if (lane == 31) wsum[wp] = x;
    __syncthreads();
    int add = 0;
    for (int w = 0; w < wp; ++w) add += wsum[w];
    if (t < NB) g_boff[t] = x - v + add;
}

__global__ void scan3_kernel() {
    int i = blockIdx.x * SCAN_B + threadIdx.x;
    if (i < NN) g_rowptr[i] += g_boff[blockIdx.x];
    if (i == 0) g_rowptr[NN] = EE;
}

__global__ void scatter_kernel(const int* __restrict__ src, const int* __restrict__ dst) {
    int i = blockIdx.x * blockDim.x + threadIdx.x;
    if (i < EE) {
        int d = dst[i];
        g_esrc[g_rowptr[d] + g_rank[i]] = src[i];
    }
}

// ------- layer-1 aggregation: warp/node, 4-edge unroll, fp16 gather -------
__global__ __launch_bounds__(256) void agg1_kernel(const float* __restrict__ b1) {
    int n = (blockIdx.x * blockDim.x + threadIdx.x) >> 5;
    int l = threadIdx.x & 31;
    if (n >= NN) return;
    int hh = l >> 3;
    float erh = g_er1[n * 4 + hh];
    int s0 = g_rowptr[n], s1 = g_rowptr[n + 1];

    const uint2* f2 = (const uint2*)g_feat1h;   // row = 32 uint2 (4 halfs each)
    ull aA0 = 0, aA1 = 0, aB0 = 0, aB1 = 0;
    float dsA = 0.f, dsB = 0.f;

    int i = s0;
    for (; i + 4 <= s1; i += 4) {
        int sa = g_esrc[i];
        int sb = g_esrc[i + 1];
        int sc = g_esrc[i + 2];
        int sd = g_esrc[i + 3];
        float ea = g_el1[sa * 4 + hh] + erh;
        float eb = g_el1[sb * 4 + hh] + erh;
        float ec = g_el1[sc * 4 + hh] + erh;
        float ed = g_el1[sd * 4 + hh] + erh;
        uint2 fa = f2[sa * 32 + l];
        uint2 fb = f2[sb * 32 + l];
        uint2 fc = f2[sc * 32 + l];
        uint2 fd = f2[sd * 32 + l];
        ea = fmaxf(ea, NEG_SLOPE * ea);
        eb = fmaxf(eb, NEG_SLOPE * eb);
        ec = fmaxf(ec, NEG_SLOPE * ec);
        ed = fmaxf(ed, NEG_SLOPE * ed);
        float wa = __expf(ea), wb = __expf(eb);
        float wc = __expf(ec), wd = __expf(ed);
        float2 fa0 = h2u_to_f2(fa.x), fa1 = h2u_to_f2(fa.y);
        float2 fb0 = h2u_to_f2(fb.x), fb1 = h2u_to_f2(fb.y);
        float2 fc0 = h2u_to_f2(fc.x), fc1 = h2u_to_f2(fc.y);
        float2 fd0 = h2u_to_f2(fd.x), fd1 = h2u_to_f2(fd.y);
        ull wa2 = pack2(wa, wa), wb2 = pack2(wb, wb);
        ull wc2 = pack2(wc, wc), wd2 = pack2(wd, wd);
        ffma2(aA0, wa2, pack2(fa0.x, fa0.y)); ffma2(aA1, wa2, pack2(fa1.x, fa1.y));
        ffma2(aB0, wb2, pack2(fb0.x, fb0.y)); ffma2(aB1, wb2, pack2(fb1.x, fb1.y));
        ffma2(aA0, wc2, pack2(fc0.x, fc0.y)); ffma2(aA1, wc2, pack2(fc1.x, fc1.y));
        ffma2(aB0, wd2, pack2(fd0.x, fd0.y)); ffma2(aB1, wd2, pack2(fd1.x, fd1.y));
        dsA += wa + wc; dsB += wb + wd;
    }
    for (; i < s1; ++i) {
        int sa = g_esrc[i];
        float ea = g_el1[sa * 4 + hh] + erh;
        ea = fmaxf(ea, NEG_SLOPE * ea);
        float wa = __expf(ea);
        uint2 fa = f2[sa * 32 + l];
        float2 fa0 = h2u_to_f2(fa.x), fa1 = h2u_to_f2(fa.y);
        ull wa2 = pack2(wa, wa);
        ffma2(aA0, wa2, pack2(fa0.x, fa0.y));
        ffma2(aA1, wa2, pack2(fa1.x, fa1.y));
        dsA += wa;
    }

    float inv = 1.0f / fmaxf(dsA + dsB, 1e-9f);
    float xA, yA, xB, yB, zA, wA, zB, wB;
    unpack2(aA0, xA, yA); unpack2(aB0, xB, yB);
    unpack2(aA1, zA, wA); unpack2(aB1, zB, wB);
    float4 bb = ((const float4*)b1)[l];
    float o0 = fmaxf((xA + xB) * inv + bb.x, 0.f);
    float o1 = fmaxf((yA + yB) * inv + bb.y, 0.f);
    float o2 = fmaxf((zA + zB) * inv + bb.z, 0.f);
    float o3 = fmaxf((wA + wB) * inv + bb.w, 0.f);
    uint2 v;
    v.x = f2_to_h2u(o0, o1);
    v.y = f2_to_h2u(o2, o3);
    ((uint2*)g_h1h)[n * 32 + l] = v;
}

// ------- GEMM2 on tensor cores: 128-row tile, fused el2/er2, fp16 out -------
__global__ __launch_bounds__(256) void gemm2_kernel(const float* __restrict__ W2,
                                                    const float* __restrict__ al2,
                                                    const float* __restrict__ ar2) {
    extern __shared__ __half smh[];
    __half* As = smh;                          // [128][A_STRIDE]
    __half* Bs = smh + G2_ROWS * A_STRIDE;     // [128][B2_STRIDE], cols 40-47 zero
    int t = threadIdx.x;
    int row0 = blockIdx.x * G2_ROWS;

    for (int i = t; i < G2_ROWS * IN_DIM / 8; i += 256) {
        int r = i >> 4, c8 = i & 15;
        int g = row0 + r;
        uint4 v = (g < NN) ? ((const uint4*)g_h1h)[g * 16 + c8]
                           : make_uint4(0u, 0u, 0u, 0u);
        *(uint4*)(As + r * A_STRIDE + c8 * 8) = v;
    }
    for (int i = t; i < IN_DIM * OUT_DIM; i += 256) {
        int r = i / OUT_DIM, c = i - r * OUT_DIM;
        Bs[r * B2_STRIDE + c] = __float2half_rn(W2[i]);
    }
    for (int i = t; i < IN_DIM * 8; i += 256) {
        int r = i >> 3, c = i & 7;
        Bs[r * B2_STRIDE + OUT_DIM + c] = __float2half_rn(0.f);
    }
    __syncthreads();

    int w = t >> 5, lane = t & 31;
    int rw = w * 16;

    uint a_base = (uint)__cvta_generic_to_shared(
        As + (rw + (lane & 15)) * A_STRIDE + ((lane >> 4) * 8));
    uint b_base = (uint)__cvta_generic_to_shared(
        Bs + (lane & 15) * B2_STRIDE + ((lane >> 4) * 8));

    float acc[6][4];
    #pragma unroll
    for (int j = 0; j < 6; ++j)
        #pragma unroll
        for (int c = 0; c < 4; ++c) acc[j][c] = 0.f;

    #pragma unroll
    for (int kb = 0; kb < 8; ++kb) {
        uint a0, a1, a2, a3;
        asm volatile("ldmatrix.sync.aligned.m8n8.x4.shared.b16 {%0,%1,%2,%3}, [%4];"
                     : "=r"(a0), "=r"(a1), "=r"(a2), "=r"(a3)
                     : "r"(a_base + kb * 32));
        #pragma unroll
        for (int p = 0; p < 3; ++p) {
            uint b0, b1, b2, b3;
            asm volatile("ldmatrix.sync.aligned.m8n8.x4.trans.shared.b16 {%0,%1,%2,%3}, [%4];"
                         : "=r"(b0), "=r"(b1), "=r"(b2), "=r"(b3)
                         : "r"(b_base + kb * 16 * B2_STRIDE * 2 + p * 32));
            asm volatile("mma.sync.aligned.m16n8k16.row.col.f32.f16.f16.f32 "
                         "{%0,%1,%2,%3}, {%4,%5,%6,%7}, {%8,%9}, {%0,%1,%2,%3};"
                         : "+f"(acc[2*p][0]), "+f"(acc[2*p][1]), "+f"(acc[2*p][2]), "+f"(acc[2*p][3])
                         : "r"(a0), "r"(a1), "r"(a2), "r"(a3), "r"(b0), "r"(b1));
            asm volatile("mma.sync.aligned.m16n8k16.row.col.f32.f16.f16.f32 "
                         "{%0,%1,%2,%3}, {%4,%5,%6,%7}, {%8,%9}, {%0,%1,%2,%3};"
                         : "+f"(acc[2*p+1][0]), "+f"(acc[2*p+1][1]), "+f"(acc[2*p+1][2]), "+f"(acc[2*p+1][3])
                         : "r"(a0), "r"(a1), "r"(a2), "r"(a3), "r"(b2), "r"(b3));
        }
    }

    int g0 = lane >> 2, quad = lane & 3;
    int r0g = row0 + rw + g0;
    int r1g = r0g + 8;

    float p0 = 0.f, p1 = 0.f, q0 = 0.f, q1 = 0.f;
    #pragma unroll
    for (int j = 0; j < 5; ++j) {
        int n0 = j * 8 + quad * 2;
        float2 av = *(const float2*)(al2 + n0);
        float2 rv = *(const float2*)(ar2 + n0);
        if (r0g < NN) ((uint*)g_feat2h)[(r0g * OUT_DIM + n0) >> 1] = f2_to_h2u(acc[j][0], acc[j][1]);
        if (r1g < NN) ((uint*)g_feat2h)[(r1g * OUT_DIM + n0) >> 1] = f2_to_h2u(acc[j][2], acc[j][3]);
        p0 += acc[j][0] * av.x + acc[j][1] * av.y;
        p1 += acc[j][2] * av.x + acc[j][3] * av.y;
        q0 += acc[j][0] * rv.x + acc[j][1] * rv.y;
        q1 += acc[j][2] * rv.x + acc[j][3] * rv.y;
    }
    #pragma unroll
    for (int off = 1; off <= 2; off <<= 1) {
        p0 += __shfl_xor_sync(0xFFFFFFFFu, p0, off);
        p1 += __shfl_xor_sync(0xFFFFFFFFu, p1, off);
        q0 += __shfl_xor_sync(0xFFFFFFFFu, q0, off);
        q1 += __shfl_xor_sync(0xFFFFFFFFu, q1, off);
    }
    if (quad == 0) {
        if (r0g < NN) { g_el2[r0g] = p0; g_er2[r0g] = q0; }
        if (r1g < NN) { g_el2[r1g] = p1; g_er2[r1g] = q1; }
    }
}

// ------- layer-2 aggregation: warp/node, 4-edge unroll, fp16 gather -------
__global__ __launch_bounds__(256) void agg2_kernel(const float* __restrict__ b2, float* __restrict__ out) {
    int n = (blockIdx.x * blockDim.x + threadIdx.x) >> 5;
    int l = threadIdx.x & 31;
    if (n >= NN) return;
    float er = g_er2[n];
    int s0 = g_rowptr[n], s1 = g_rowptr[n + 1];
    int lc = (l < 20) ? l : 19;

    const uint* f2 = (const uint*)g_feat2h;   // row = 20 uints (2 halfs each)
    ull aA = 0, aB = 0;
    float dsA = 0.f, dsB = 0.f;

    int i = s0;
    for (; i + 4 <= s1; i += 4) {
        int sa = g_esrc[i];
        int sb = g_esrc[i + 1];
        int sc = g_esrc[i + 2];
        int sd = g_esrc[i + 3];
        float ea = g_el2[sa] + er;
        float eb = g_el2[sb] + er;
        float ec = g_el2[sc] + er;
        float ed = g_el2[sd] + er;
        uint fa = f2[sa * 20 + lc];
        uint fb = f2[sb * 20 + lc];
        uint fc = f2[sc * 20 + lc];
        uint fd = f2[sd * 20 + lc];
        ea = fmaxf(ea, NEG_SLOPE * ea);
        eb = fmaxf(eb, NEG_SLOPE * eb);
        ec = fmaxf(ec, NEG_SLOPE * ec);
        ed = fmaxf(ed, NEG_SLOPE * ed);
        float wa = __expf(ea), wb = __expf(eb);
        float wc = __expf(ec), wd = __expf(ed);
        float2 fav = h2u_to_f2(fa), fbv = h2u_to_f2(fb);
        float2 fcv = h2u_to_f2(fc), fdv = h2u_to_f2(fd);
        ffma2(aA, pack2(wa, wa), pack2(fav.x, fav.y));
        ffma2(aB, pack2(wb, wb), pack2(fbv.x, fbv.y));
        ffma2(aA, pack2(wc, wc), pack2(fcv.x, fcv.y));
        ffma2(aB, pack2(wd, wd), pack2(fdv.x, fdv.y));
        dsA += wa + wc; dsB += wb + wd;
    }
    for (; i < s1; ++i) {
        int sa = g_esrc[i];
        float ea = g_el2[sa] + er;
        ea = fmaxf(ea, NEG_SLOPE * ea);
        float wa = __expf(ea);
        float2 fav = h2u_to_f2(f2[sa * 20 + lc]);
        ffma2(aA, pack2(wa, wa), pack2(fav.x, fav.y));
        dsA += wa;
    }

    if (l < 20) {
        float inv = 1.0f / fmaxf(dsA + dsB, 1e-9f);
        float xa, ya, xb, yb;
        unpack2(aA, xa, ya); unpack2(aB, xb, yb);
        float o0 = (xa + xb) * inv + b2[2 * l];
        float o1 = (ya + yb) * inv + b2[2 * l + 1];
        ((ull*)out)[n * 20 + l] = pack2(o0, o1);
    }
}

// ---------------- side stream for CSR/GEMM1 overlap ----------------
namespace {
struct Aux {
    cudaStream_t s2;
    cudaEvent_t fork, join;
    bool ok;
    Aux() : s2(nullptr), fork(nullptr), join(nullptr), ok(false) {
        if (cudaStreamCreateWithFlags(&s2, cudaStreamNonBlocking) != cudaSuccess) return;
        if (cudaEventCreateWithFlags(&fork, cudaEventDisableTiming) != cudaSuccess) return;
        if (cudaEventCreateWithFlags(&join, cudaEventDisableTiming) != cudaSuccess) return;
        ok = true;
    }
};
Aux g_aux;
}

// ---------------- launch ----------------
extern "C" void kernel_launch(void* const* d_in, const int* in_sizes, int n_in,
                              void* d_out, int out_size) {
    const float* h   = (const float*)d_in[0];
    const int*   src = (const int*)  d_in[1];
    const int*   dst = (const int*)  d_in[2];
    const float* W1  = (const float*)d_in[3];
    const float* al1 = (const float*)d_in[4];
    const float* ar1 = (const float*)d_in[5];
    const float* b1  = (const float*)d_in[6];
    const float* W2  = (const float*)d_in[7];
    const float* al2 = (const float*)d_in[8];
    const float* ar2 = (const float*)d_in[9];
    const float* b2  = (const float*)d_in[10];
    float* out = (float*)d_out;

    cudaFuncSetAttribute(gemm1_kernel, cudaFuncAttributeMaxDynamicSharedMemorySize, G1_SMEM);
    cudaFuncSetAttribute(gemm2_kernel, cudaFuncAttributeMaxDynamicSharedMemorySize, G2_SMEM);

    int nwarp_blocks = (NN * 32 + 255) / 256;
    int eblocks = (EE + 255) / 256;
    int g1blocks = (NN + G1_ROWS - 1) / G1_ROWS;
    int g2blocks = (NN + G2_ROWS - 1) / G2_ROWS;

    if (g_aux.ok) {
        cudaEventRecord(g_aux.fork, 0);
        cudaStreamWaitEvent(g_aux.s2, g_aux.fork, 0);
        zero_kernel<<<(NN + 255) / 256, 256, 0, g_aux.s2>>>();            // 1
        hist_kernel<<<eblocks, 256, 0, g_aux.s2>>>(dst);                  // 2
        w1cvt_kernel<<<(IN_DIM * IN_DIM / 2 + 255) / 256, 256>>>(W1);     // 3 (main)
        gemm1_kernel<<<g1blocks, 512, G1_SMEM>>>(h, al1, ar1);            // 4 (main, profiled)
        scan1_kernel<<<NB, SCAN_B, 0, g_aux.s2>>>();                      // 5
        scan2_kernel<<<1, 128, 0, g_aux.s2>>>();                          // 6
        scan3_kernel<<<NB, SCAN_B, 0, g_aux.s2>>>();                      // 7
        scatter_kernel<<<eblocks, 256, 0, g_aux.s2>>>(src, dst);          // 8
        cudaEventRecord(g_aux.join, g_aux.s2);
        cudaStreamWaitEvent(0, g_aux.join, 0);
    } else {
        zero_kernel<<<(NN + 255) / 256, 256>>>();
        hist_kernel<<<eblocks, 256>>>(dst);
        w1cvt_kernel<<<(IN_DIM * IN_DIM / 2 + 255) / 256, 256>>>(W1);
        gemm1_kernel<<<g1blocks, 512, G1_SMEM>>>(h, al1, ar1);
        scan1_kernel<<<NB, SCAN_B>>>();
        scan2_kernel<<<1, 128>>>();
        scan3_kernel<<<NB, SCAN_B>>>();
        scatter_kernel<<<eblocks, 256>>>(src, dst);
    }

    agg1_kernel<<<nwarp_blocks, 256>>>(b1);
    gemm2_kernel<<<g2blocks, 256, G2_SMEM>>>(W2, al2, ar2);
    agg2_kernel<<<nwarp_blocks, 256>>>(b2, out);
}